// round 1
// baseline (speedup 1.0000x reference)
#include <cuda_runtime.h>
#include <math.h>

#define BATCH  2
#define SEQ    2048
#define ROWS   (BATCH*SEQ)     // 4096
#define HIDDEN 512
#define QKVP   3584            // HIDDEN*(3+EXP)
#define VP     2560            // HIDDEN*(1+EXP)
#define HEADS  8
#define HD     64

// ---------------- scratch (no cudaMalloc allowed) ----------------
__device__ float g_xn[(size_t)ROWS*HIDDEN];          //  8 MB
__device__ float g_xt[(size_t)ROWS*HIDDEN];          //  8 MB
__device__ float g_proj[(size_t)ROWS*QKVP];          // 58.7 MB
__device__ float g_cat[(size_t)ROWS*VP];             // 41.9 MB

// ---------------- LayerNorm: one block per row ----------------
__global__ void __launch_bounds__(128) ln_kernel(const float* __restrict__ x,
                                                 const float* __restrict__ gamma,
                                                 const float* __restrict__ beta)
{
    int row = blockIdx.x;
    int tid = threadIdx.x;                 // 128 threads, 4 elems each
    const float* xr = x + (size_t)row*HIDDEN;
    float v[4];
    float s = 0.f;
    #pragma unroll
    for (int i = 0; i < 4; i++) { v[i] = xr[tid + i*128]; s += v[i]; }
    __shared__ float red[4];
    #pragma unroll
    for (int o = 16; o > 0; o >>= 1) s += __shfl_xor_sync(0xffffffffu, s, o);
    if ((tid & 31) == 0) red[tid >> 5] = s;
    __syncthreads();
    float mu = (red[0]+red[1]+red[2]+red[3]) * (1.f/HIDDEN);
    float vs = 0.f;
    #pragma unroll
    for (int i = 0; i < 4; i++) { float d = v[i]-mu; vs += d*d; }
    #pragma unroll
    for (int o = 16; o > 0; o >>= 1) vs += __shfl_xor_sync(0xffffffffu, vs, o);
    __syncthreads();
    if ((tid & 31) == 0) red[tid >> 5] = vs;
    __syncthreads();
    float var  = (red[0]+red[1]+red[2]+red[3]) * (1.f/HIDDEN);
    float rstd = rsqrtf(var + 1e-5f);
    #pragma unroll
    for (int i = 0; i < 4; i++) {
        int c = tid + i*128;
        g_xn[(size_t)row*HIDDEN + c] = (v[i]-mu)*rstd*gamma[c] + beta[c];
    }
}

// ---------------- feature transform: ident + shifts ----------------
__global__ void feat_kernel()
{
    int idx = blockIdx.x*256 + threadIdx.x;
    if (idx >= ROWS*HIDDEN) return;
    int c   = idx & 511;
    int row = idx >> 9;
    int i   = row & (SEQ-1);
    float val;
    if (c < 320)       val = g_xn[idx];
    else if (c < 384)  return;                                   // scan kernel owns these
    else if (c < 448)  val = (i >= 1) ? g_xn[idx -   HIDDEN] : 0.f;
    else               val = (i >= 2) ? g_xn[idx - 2*HIDDEN] : 0.f;
    g_xt[idx] = val;
}

// ---------------- cumlogsumexp scan: block per (batch, channel) ----------------
__global__ void __launch_bounds__(256) scan_kernel()
{
    int bc  = blockIdx.x;           // 0..127
    int b   = bc >> 6;
    int ch  = 320 + (bc & 63);
    int tid = threadIdx.x;          // 256 threads * 8 elems = 2048
    int row0 = b*SEQ + tid*8;
    float y[8];
    #pragma unroll
    for (int i = 0; i < 8; i++) y[i] = 5.f * g_xn[(size_t)(row0+i)*HIDDEN + ch];
    // thread-local aggregate (m, s)
    float m = -INFINITY, s = 0.f;
    #pragma unroll
    for (int i = 0; i < 8; i++) {
        float M = fmaxf(m, y[i]);
        s = s*expf(m - M) + expf(y[i] - M);
        m = M;
    }
    // Hillis-Steele inclusive scan of (m, s) pairs
    __shared__ float sm[256], ss[256];
    sm[tid] = m; ss[tid] = s;
    __syncthreads();
    for (int off = 1; off < 256; off <<= 1) {
        float pm = 0.f, ps = 0.f;
        bool act = (tid >= off);
        if (act) { pm = sm[tid-off]; ps = ss[tid-off]; }
        __syncthreads();
        if (act) {
            float M = fmaxf(pm, m);
            s = ps*expf(pm - M) + s*expf(m - M);
            m = M;
            sm[tid] = m; ss[tid] = s;
        }
        __syncthreads();
    }
    // exclusive prefix for this thread
    float pm = -INFINITY, ps = 0.f;
    if (tid > 0) { pm = sm[tid-1]; ps = ss[tid-1]; }
    #pragma unroll
    for (int i = 0; i < 8; i++) {
        float M = fmaxf(pm, y[i]);
        ps = ps*expf(pm - M) + expf(y[i] - M);
        pm = M;
        g_xt[(size_t)(row0+i)*HIDDEN + ch] = (pm + logf(ps)) * 0.2f;
    }
}

// ---------------- fp32 SGEMM, 128x128 tile, K-step 8, 8x8 microtile ----------------
__global__ void __launch_bounds__(256) sgemm_kernel(
    const float* __restrict__ A, const float* __restrict__ B,
    float* __restrict__ C, const float* __restrict__ bias,
    int K, int lda, int ldb, int ldc)
{
    __shared__ float As[8][128];
    __shared__ float Bs[8][128];
    int tid = threadIdx.x;
    int m0 = blockIdx.y * 128;
    int n0 = blockIdx.x * 128;
    int aRow = tid >> 1;
    int aCol = (tid & 1) << 2;
    int bRow = tid >> 5;
    int bCol = (tid & 31) << 2;
    const float* Ap = A + (size_t)(m0 + aRow)*lda + aCol;
    const float* Bp = B + (size_t)bRow*ldb + n0 + bCol;
    int ty = tid >> 4, tx = tid & 15;
    float acc[8][8];
    #pragma unroll
    for (int i = 0; i < 8; i++)
        #pragma unroll
        for (int j = 0; j < 8; j++) acc[i][j] = 0.f;

    for (int k0 = 0; k0 < K; k0 += 8) {
        float4 av = *(const float4*)Ap; Ap += 8;
        float4 bv = *(const float4*)Bp; Bp += (size_t)8*ldb;
        __syncthreads();
        As[aCol+0][aRow] = av.x;
        As[aCol+1][aRow] = av.y;
        As[aCol+2][aRow] = av.z;
        As[aCol+3][aRow] = av.w;
        *(float4*)&Bs[bRow][bCol] = bv;
        __syncthreads();
        #pragma unroll
        for (int kk = 0; kk < 8; kk++) {
            float a[8], bb[8];
            *(float4*)&a[0]  = *(const float4*)&As[kk][ty*8];
            *(float4*)&a[4]  = *(const float4*)&As[kk][ty*8+4];
            *(float4*)&bb[0] = *(const float4*)&Bs[kk][tx*8];
            *(float4*)&bb[4] = *(const float4*)&Bs[kk][tx*8+4];
            #pragma unroll
            for (int i = 0; i < 8; i++)
                #pragma unroll
                for (int j = 0; j < 8; j++) acc[i][j] += a[i]*bb[j];
        }
    }
    #pragma unroll
    for (int i = 0; i < 8; i++) {
        int mrow = m0 + ty*8 + i;
        float* Cr = C + (size_t)mrow*ldc + n0 + tx*8;
        #pragma unroll
        for (int j = 0; j < 8; j++) {
            float val = acc[i][j];
            if (bias) val += bias[n0 + tx*8 + j];
            Cr[j] = val;
        }
    }
}

// ---------------- exact GELU on the P slice -> g_cat[:,512:] ----------------
__global__ void gelu_kernel()
{
    int idx = blockIdx.x*256 + threadIdx.x;
    if (idx >= ROWS*2048) return;
    int row = idx >> 11;
    int c   = idx & 2047;
    float xv = g_proj[(size_t)row*QKVP + 1536 + c];
    g_cat[(size_t)row*VP + 512 + c] = 0.5f*xv*(1.f + erff(xv*0.70710678118654752f));
}

// ---------------- flash attention (fp32), Br=64 Bc=32, causal + ALiBi ----------------
__global__ void __launch_bounds__(256) attn_kernel()
{
    const int q0 = blockIdx.x * 64;
    const int h  = blockIdx.y;
    const int b  = blockIdx.z;
    __shared__ float Qs[64][68];
    __shared__ float Ks[32][68];
    __shared__ float Vs[32][68];
    __shared__ float Ss[64][33];
    int tid = threadIdx.x;       // 256
    int r   = tid >> 2;          // query row within tile, 0..63
    int cg  = tid & 3;           // column/dim subgroup, 0..3
    const float scale = 0.125f;  // 1/sqrt(64)
    const float slope = exp2f(-(float)(h+1));   // ALiBi slope, H=8 power-of-two case

    for (int idx = tid; idx < 64*64; idx += 256) {
        int rr = idx >> 6, d = idx & 63;
        Qs[rr][d] = g_proj[(size_t)(b*SEQ + q0 + rr)*QKVP + h*HD + d];
    }
    float o[16];
    #pragma unroll
    for (int i = 0; i < 16; i++) o[i] = 0.f;
    float m = -INFINITY, l = 0.f;
    int ig = q0 + r;

    for (int j0 = 0; j0 <= q0 + 32; j0 += 32) {
        __syncthreads();
        for (int idx = tid; idx < 32*64; idx += 256) {
            int rr = idx >> 6, d = idx & 63;
            size_t rowb = (size_t)(b*SEQ + j0 + rr)*QKVP + h*HD + d;
            Ks[rr][d] = g_proj[rowb + 512];
            Vs[rr][d] = g_proj[rowb + 1024];
        }
        __syncthreads();

        // scores for my 8 columns c = cg + 4k
        float sv[8];
        #pragma unroll
        for (int k = 0; k < 8; k++) sv[k] = 0.f;
        #pragma unroll
        for (int d = 0; d < 64; d += 4) {
            float4 q4 = *(const float4*)&Qs[r][d];
            #pragma unroll
            for (int k = 0; k < 8; k++) {
                int c = cg + 4*k;
                float4 k4 = *(const float4*)&Ks[c][d];
                sv[k] += q4.x*k4.x + q4.y*k4.y + q4.z*k4.z + q4.w*k4.w;
            }
        }
        float tmax = -INFINITY;
        #pragma unroll
        for (int k = 0; k < 8; k++) {
            int j = j0 + cg + 4*k;
            sv[k] = (j <= ig) ? (sv[k]*scale + slope*(float)j) : -INFINITY;
            tmax = fmaxf(tmax, sv[k]);
        }
        tmax = fmaxf(tmax, __shfl_xor_sync(0xffffffffu, tmax, 1));
        tmax = fmaxf(tmax, __shfl_xor_sync(0xffffffffu, tmax, 2));
        float nm   = fmaxf(m, tmax);          // finite after first tile (j=0..31 always has j<=ig)
        float corr = expf(m - nm);            // expf(-inf)=0 on first tile
        float psum = 0.f;
        #pragma unroll
        for (int k = 0; k < 8; k++) {
            float p = expf(sv[k] - nm);
            Ss[r][cg + 4*k] = p;
            psum += p;
        }
        psum += __shfl_xor_sync(0xffffffffu, psum, 1);
        psum += __shfl_xor_sync(0xffffffffu, psum, 2);
        l = l*corr + psum;
        m = nm;
        #pragma unroll
        for (int i = 0; i < 16; i++) o[i] *= corr;
        __syncwarp();   // Ss row r written by the 4 threads of this group (same warp)

        // O += P @ V for my 16 dims (cg*16 .. cg*16+15)
        #pragma unroll 4
        for (int j = 0; j < 32; j++) {
            float p = Ss[r][j];
            float4 v0 = *(const float4*)&Vs[j][cg*16];
            float4 v1 = *(const float4*)&Vs[j][cg*16+4];
            float4 v2 = *(const float4*)&Vs[j][cg*16+8];
            float4 v3 = *(const float4*)&Vs[j][cg*16+12];
            o[0]  += p*v0.x; o[1]  += p*v0.y; o[2]  += p*v0.z; o[3]  += p*v0.w;
            o[4]  += p*v1.x; o[5]  += p*v1.y; o[6]  += p*v1.z; o[7]  += p*v1.w;
            o[8]  += p*v2.x; o[9]  += p*v2.y; o[10] += p*v2.z; o[11] += p*v2.w;
            o[12] += p*v3.x; o[13] += p*v3.y; o[14] += p*v3.z; o[15] += p*v3.w;
        }
    }
    float inv = 1.f / l;
    size_t orow = (size_t)(b*SEQ + q0 + r)*VP + h*HD + cg*16;
    #pragma unroll
    for (int i = 0; i < 16; i++) g_cat[orow + i] = o[i]*inv;
}

// ---------------- launch ----------------
extern "C" void kernel_launch(void* const* d_in, const int* in_sizes, int n_in,
                              void* d_out, int out_size)
{
    (void)in_sizes; (void)n_in; (void)out_size;
    const float* x     = (const float*)d_in[0];
    const float* gamma = (const float*)d_in[1];
    const float* beta  = (const float*)d_in[2];
    const float* w_in  = (const float*)d_in[3];
    const float* w_out = (const float*)d_in[4];
    const float* b_out = (const float*)d_in[5];
    float* out = (float*)d_out;

    float *p_xt, *p_proj, *p_cat;
    cudaGetSymbolAddress((void**)&p_xt,   g_xt);
    cudaGetSymbolAddress((void**)&p_proj, g_proj);
    cudaGetSymbolAddress((void**)&p_cat,  g_cat);

    ln_kernel<<<ROWS, 128>>>(x, gamma, beta);
    feat_kernel<<<(ROWS*HIDDEN + 255)/256, 256>>>();
    scan_kernel<<<BATCH*64, 256>>>();

    dim3 g1(QKVP/128, ROWS/128);     // (28, 32)
    sgemm_kernel<<<g1, 256>>>(p_xt, w_in, p_proj, nullptr, HIDDEN, HIDDEN, QKVP, QKVP);

    gelu_kernel<<<(ROWS*2048 + 255)/256, 256>>>();
    attn_kernel<<<dim3(SEQ/64, HEADS, BATCH), 256>>>();

    dim3 g2(HIDDEN/128, ROWS/128);   // (4, 32)
    sgemm_kernel<<<g2, 256>>>(p_cat, w_out, out, b_out, VP, VP, HIDDEN, HIDDEN);
}

// round 2
// speedup vs baseline: 2.0114x; 2.0114x over previous
#include <cuda_runtime.h>
#include <math.h>
#include <stdint.h>

#define BATCH  2
#define SEQ    2048
#define ROWS   (BATCH*SEQ)     // 4096
#define HIDDEN 512
#define QKVP   3584            // HIDDEN*(3+EXP)
#define VP     2560            // HIDDEN*(1+EXP)
#define HEADS  8
#define HD     64

// ---------------- scratch (no cudaMalloc allowed) ----------------
__device__ float g_xn[(size_t)ROWS*HIDDEN];          //  8 MB
__device__ float g_xt[(size_t)ROWS*HIDDEN];          //  8 MB
__device__ float g_proj[(size_t)ROWS*QKVP];          // 58.7 MB
__device__ float g_cat[(size_t)ROWS*VP];             // 41.9 MB

// ---------------- LayerNorm: one block per row ----------------
__global__ void __launch_bounds__(128) ln_kernel(const float* __restrict__ x,
                                                 const float* __restrict__ gamma,
                                                 const float* __restrict__ beta)
{
    int row = blockIdx.x;
    int tid = threadIdx.x;                 // 128 threads, 4 elems each
    const float* xr = x + (size_t)row*HIDDEN;
    float v[4];
    float s = 0.f;
    #pragma unroll
    for (int i = 0; i < 4; i++) { v[i] = xr[tid + i*128]; s += v[i]; }
    __shared__ float red[4];
    #pragma unroll
    for (int o = 16; o > 0; o >>= 1) s += __shfl_xor_sync(0xffffffffu, s, o);
    if ((tid & 31) == 0) red[tid >> 5] = s;
    __syncthreads();
    float mu = (red[0]+red[1]+red[2]+red[3]) * (1.f/HIDDEN);
    float vs = 0.f;
    #pragma unroll
    for (int i = 0; i < 4; i++) { float d = v[i]-mu; vs += d*d; }
    #pragma unroll
    for (int o = 16; o > 0; o >>= 1) vs += __shfl_xor_sync(0xffffffffu, vs, o);
    __syncthreads();
    if ((tid & 31) == 0) red[tid >> 5] = vs;
    __syncthreads();
    float var  = (red[0]+red[1]+red[2]+red[3]) * (1.f/HIDDEN);
    float rstd = rsqrtf(var + 1e-5f);
    #pragma unroll
    for (int i = 0; i < 4; i++) {
        int c = tid + i*128;
        g_xn[(size_t)row*HIDDEN + c] = (v[i]-mu)*rstd*gamma[c] + beta[c];
    }
}

// ---------------- feature transform: ident + shifts ----------------
__global__ void feat_kernel()
{
    int idx = blockIdx.x*256 + threadIdx.x;
    if (idx >= ROWS*HIDDEN) return;
    int c   = idx & 511;
    int row = idx >> 9;
    int i   = row & (SEQ-1);
    float val;
    if (c < 320)       val = g_xn[idx];
    else if (c < 384)  return;                                   // scan kernel owns these
    else if (c < 448)  val = (i >= 1) ? g_xn[idx -   HIDDEN] : 0.f;
    else               val = (i >= 2) ? g_xn[idx - 2*HIDDEN] : 0.f;
    g_xt[idx] = val;
}

// ---------------- cumlogsumexp scan: block per (batch, channel) ----------------
__global__ void __launch_bounds__(256) scan_kernel()
{
    int bc  = blockIdx.x;           // 0..127
    int b   = bc >> 6;
    int ch  = 320 + (bc & 63);
    int tid = threadIdx.x;          // 256 threads * 8 elems = 2048
    int row0 = b*SEQ + tid*8;
    float y[8];
    #pragma unroll
    for (int i = 0; i < 8; i++) y[i] = 5.f * g_xn[(size_t)(row0+i)*HIDDEN + ch];
    // thread-local aggregate (m, s)
    float m = -INFINITY, s = 0.f;
    #pragma unroll
    for (int i = 0; i < 8; i++) {
        float M = fmaxf(m, y[i]);
        s = s*expf(m - M) + expf(y[i] - M);
        m = M;
    }
    // Hillis-Steele inclusive scan of (m, s) pairs
    __shared__ float sm[256], ss[256];
    sm[tid] = m; ss[tid] = s;
    __syncthreads();
    for (int off = 1; off < 256; off <<= 1) {
        float pm = 0.f, ps = 0.f;
        bool act = (tid >= off);
        if (act) { pm = sm[tid-off]; ps = ss[tid-off]; }
        __syncthreads();
        if (act) {
            float M = fmaxf(pm, m);
            s = ps*expf(pm - M) + s*expf(m - M);
            m = M;
            sm[tid] = m; ss[tid] = s;
        }
        __syncthreads();
    }
    // exclusive prefix for this thread
    float pm = -INFINITY, ps = 0.f;
    if (tid > 0) { pm = sm[tid-1]; ps = ss[tid-1]; }
    #pragma unroll
    for (int i = 0; i < 8; i++) {
        float M = fmaxf(pm, y[i]);
        ps = ps*expf(pm - M) + expf(y[i] - M);
        pm = M;
        g_xt[(size_t)(row0+i)*HIDDEN + ch] = (pm + logf(ps)) * 0.2f;
    }
}

// ---------------- fp32 SGEMM, 128x128 tile, K-step 8, 8x8 microtile ----------------
__global__ void __launch_bounds__(256) sgemm_kernel(
    const float* __restrict__ A, const float* __restrict__ B,
    float* __restrict__ C, const float* __restrict__ bias,
    int K, int lda, int ldb, int ldc)
{
    __shared__ float As[8][128];
    __shared__ float Bs[8][128];
    int tid = threadIdx.x;
    int m0 = blockIdx.y * 128;
    int n0 = blockIdx.x * 128;
    int aRow = tid >> 1;
    int aCol = (tid & 1) << 2;
    int bRow = tid >> 5;
    int bCol = (tid & 31) << 2;
    const float* Ap = A + (size_t)(m0 + aRow)*lda + aCol;
    const float* Bp = B + (size_t)bRow*ldb + n0 + bCol;
    int ty = tid >> 4, tx = tid & 15;
    float acc[8][8];
    #pragma unroll
    for (int i = 0; i < 8; i++)
        #pragma unroll
        for (int j = 0; j < 8; j++) acc[i][j] = 0.f;

    for (int k0 = 0; k0 < K; k0 += 8) {
        float4 av = *(const float4*)Ap; Ap += 8;
        float4 bv = *(const float4*)Bp; Bp += (size_t)8*ldb;
        __syncthreads();
        As[aCol+0][aRow] = av.x;
        As[aCol+1][aRow] = av.y;
        As[aCol+2][aRow] = av.z;
        As[aCol+3][aRow] = av.w;
        *(float4*)&Bs[bRow][bCol] = bv;
        __syncthreads();
        #pragma unroll
        for (int kk = 0; kk < 8; kk++) {
            float a[8], bb[8];
            *(float4*)&a[0]  = *(const float4*)&As[kk][ty*8];
            *(float4*)&a[4]  = *(const float4*)&As[kk][ty*8+4];
            *(float4*)&bb[0] = *(const float4*)&Bs[kk][tx*8];
            *(float4*)&bb[4] = *(const float4*)&Bs[kk][tx*8+4];
            #pragma unroll
            for (int i = 0; i < 8; i++)
                #pragma unroll
                for (int j = 0; j < 8; j++) acc[i][j] += a[i]*bb[j];
        }
    }
    #pragma unroll
    for (int i = 0; i < 8; i++) {
        int mrow = m0 + ty*8 + i;
        float* Cr = C + (size_t)mrow*ldc + n0 + tx*8;
        #pragma unroll
        for (int j = 0; j < 8; j++) {
            float val = acc[i][j];
            if (bias) val += bias[n0 + tx*8 + j];
            Cr[j] = val;
        }
    }
}

// ---------------- exact GELU on the P slice -> g_cat[:,512:] ----------------
__global__ void gelu_kernel()
{
    int idx = blockIdx.x*256 + threadIdx.x;
    if (idx >= ROWS*2048) return;
    int row = idx >> 11;
    int c   = idx & 2047;
    float xv = g_proj[(size_t)row*QKVP + 1536 + c];
    g_cat[(size_t)row*VP + 512 + c] = 0.5f*xv*(1.f + erff(xv*0.70710678118654752f));
}

// ---------------- tf32 helpers ----------------
__device__ __forceinline__ float f2tf32(float x) {
    uint32_t r;
    asm("cvt.rna.tf32.f32 %0, %1;" : "=r"(r) : "f"(x));
    return __uint_as_float(r);
}
__device__ __forceinline__ void mma_tf32(float* d, const uint32_t* a, uint32_t b0, uint32_t b1) {
    asm volatile("mma.sync.aligned.m16n8k8.row.col.f32.tf32.tf32.f32 "
        "{%0,%1,%2,%3}, {%4,%5,%6,%7}, {%8,%9}, {%0,%1,%2,%3};"
        : "+f"(d[0]), "+f"(d[1]), "+f"(d[2]), "+f"(d[3])
        : "r"(a[0]), "r"(a[1]), "r"(a[2]), "r"(a[3]), "r"(b0), "r"(b1));
}

// ---------------- flash attention, tf32 mma.sync, Bq=64 Bc=64 ----------------
// 128 threads = 4 warps; warp w owns q-rows [w*16, w*16+16)
// Smem: Ks[64][68] (also Q staging), Vs[64][72], Ps[64][68]
#define KS_STRIDE 68
#define VS_STRIDE 72
__global__ void __launch_bounds__(128) attn_mma_kernel()
{
    extern __shared__ float smem[];
    float* Ks = smem;                       // 64*68
    float* Vs = smem + 64*KS_STRIDE;        // 64*72
    float* Ps = Vs + 64*VS_STRIDE;          // 64*68

    const int qb = blockIdx.x;
    const int h  = blockIdx.y;
    const int b  = blockIdx.z;
    const int q0 = qb*64;
    const int tid  = threadIdx.x;
    const int warp = tid >> 5;
    const int lane = tid & 31;
    const int gq = lane >> 2;    // 0..7 : fragment row within 8
    const int qd = lane & 3;     // 0..3 : quad index

    const float scale = 0.125f;  // 1/sqrt(64)
    const float slope = exp2f(-(float)(h+1));

    // ---- stage Q tile (tf32-rounded) into Ks buffer, coalesced
    for (int idx = tid; idx < 64*16; idx += 128) {
        int rr = idx >> 4, d4 = (idx & 15) << 2;
        float4 v = *(const float4*)&g_proj[(size_t)(b*SEQ + q0 + rr)*QKVP + h*HD + d4];
        float* dst = &Ks[rr*KS_STRIDE + d4];
        dst[0] = f2tf32(v.x); dst[1] = f2tf32(v.y);
        dst[2] = f2tf32(v.z); dst[3] = f2tf32(v.w);
    }
    __syncthreads();

    // ---- read Q fragments to registers (held for whole kernel)
    uint32_t qf[8][4];
    {
        int r0 = warp*16 + gq;
        #pragma unroll
        for (int kt = 0; kt < 8; kt++) {
            int k0 = kt*8;
            qf[kt][0] = __float_as_uint(Ks[ r0     *KS_STRIDE + k0 + qd    ]);
            qf[kt][1] = __float_as_uint(Ks[(r0+8)  *KS_STRIDE + k0 + qd    ]);
            qf[kt][2] = __float_as_uint(Ks[ r0     *KS_STRIDE + k0 + qd + 4]);
            qf[kt][3] = __float_as_uint(Ks[(r0+8)  *KS_STRIDE + k0 + qd + 4]);
        }
    }
    __syncthreads();

    float o[8][4];
    #pragma unroll
    for (int t = 0; t < 8; t++) { o[t][0]=0.f; o[t][1]=0.f; o[t][2]=0.f; o[t][3]=0.f; }
    float m0 = -INFINITY, m1 = -INFINITY, l0 = 0.f, l1 = 0.f;
    const int i0 = q0 + warp*16 + gq;   // global q row for frag slots 0,1
    const int i1 = i0 + 8;              // for slots 2,3
    const int prow0 = (warp*16 + gq)*KS_STRIDE;
    const int prow1 = (warp*16 + gq + 8)*KS_STRIDE;

    const int ntiles = qb + 1;
    for (int jt = 0; jt < ntiles; jt++) {
        const int j0 = jt*64;
        // load K,V tiles (tf32-rounded), coalesced
        for (int idx = tid; idx < 64*16; idx += 128) {
            int rr = idx >> 4, d4 = (idx & 15) << 2;
            size_t base = (size_t)(b*SEQ + j0 + rr)*QKVP + h*HD + d4;
            float4 kv = *(const float4*)&g_proj[base + 512];
            float4 vv = *(const float4*)&g_proj[base + 1024];
            float* kd = &Ks[rr*KS_STRIDE + d4];
            kd[0]=f2tf32(kv.x); kd[1]=f2tf32(kv.y); kd[2]=f2tf32(kv.z); kd[3]=f2tf32(kv.w);
            float* vd = &Vs[rr*VS_STRIDE + d4];
            vd[0]=f2tf32(vv.x); vd[1]=f2tf32(vv.y); vd[2]=f2tf32(vv.z); vd[3]=f2tf32(vv.w);
        }
        __syncthreads();

        // ---- S = Q @ K^T  (16x64 per warp)
        float s[8][4];
        #pragma unroll
        for (int t = 0; t < 8; t++) { s[t][0]=0.f; s[t][1]=0.f; s[t][2]=0.f; s[t][3]=0.f; }
        #pragma unroll
        for (int kt = 0; kt < 8; kt++) {
            int k0 = kt*8;
            #pragma unroll
            for (int nt = 0; nt < 8; nt++) {
                int n0 = nt*8;
                uint32_t b0 = __float_as_uint(Ks[(n0+gq)*KS_STRIDE + k0 + qd    ]);
                uint32_t b1 = __float_as_uint(Ks[(n0+gq)*KS_STRIDE + k0 + qd + 4]);
                mma_tf32(s[nt], qf[kt], b0, b1);
            }
        }

        // ---- mask + scale + alibi, online softmax
        float rm0 = -INFINITY, rm1 = -INFINITY;
        #pragma unroll
        for (int nt = 0; nt < 8; nt++) {
            int j = j0 + nt*8 + 2*qd;
            s[nt][0] = (j   <= i0) ? fmaf(s[nt][0], scale, slope*(float)j    ) : -1e30f;
            s[nt][1] = (j+1 <= i0) ? fmaf(s[nt][1], scale, slope*(float)(j+1)) : -1e30f;
            s[nt][2] = (j   <= i1) ? fmaf(s[nt][2], scale, slope*(float)j    ) : -1e30f;
            s[nt][3] = (j+1 <= i1) ? fmaf(s[nt][3], scale, slope*(float)(j+1)) : -1e30f;
            rm0 = fmaxf(rm0, fmaxf(s[nt][0], s[nt][1]));
            rm1 = fmaxf(rm1, fmaxf(s[nt][2], s[nt][3]));
        }
        rm0 = fmaxf(rm0, __shfl_xor_sync(0xffffffffu, rm0, 1));
        rm0 = fmaxf(rm0, __shfl_xor_sync(0xffffffffu, rm0, 2));
        rm1 = fmaxf(rm1, __shfl_xor_sync(0xffffffffu, rm1, 1));
        rm1 = fmaxf(rm1, __shfl_xor_sync(0xffffffffu, rm1, 2));
        float nm0 = fmaxf(m0, rm0), nm1 = fmaxf(m1, rm1);
        float c0 = __expf(m0 - nm0), c1 = __expf(m1 - nm1);
        m0 = nm0; m1 = nm1;
        float ps0 = 0.f, ps1 = 0.f;
        #pragma unroll
        for (int nt = 0; nt < 8; nt++) {
            float p0 = __expf(s[nt][0] - nm0);
            float p1 = __expf(s[nt][1] - nm0);
            float p2 = __expf(s[nt][2] - nm1);
            float p3 = __expf(s[nt][3] - nm1);
            ps0 += p0 + p1;  ps1 += p2 + p3;
            int cl = nt*8 + 2*qd;
            *(float2*)&Ps[prow0 + cl] = make_float2(f2tf32(p0), f2tf32(p1));
            *(float2*)&Ps[prow1 + cl] = make_float2(f2tf32(p2), f2tf32(p3));
            o[nt][0] *= c0; o[nt][1] *= c0; o[nt][2] *= c1; o[nt][3] *= c1;
        }
        ps0 += __shfl_xor_sync(0xffffffffu, ps0, 1);
        ps0 += __shfl_xor_sync(0xffffffffu, ps0, 2);
        ps1 += __shfl_xor_sync(0xffffffffu, ps1, 1);
        ps1 += __shfl_xor_sync(0xffffffffu, ps1, 2);
        l0 = l0*c0 + ps0;
        l1 = l1*c1 + ps1;
        __syncwarp();

        // ---- O += P @ V   (16x64 per warp)
        #pragma unroll
        for (int kt = 0; kt < 8; kt++) {
            int k0 = kt*8;
            uint32_t pa[4];
            pa[0] = __float_as_uint(Ps[prow0 + k0 + qd    ]);
            pa[1] = __float_as_uint(Ps[prow1 + k0 + qd    ]);
            pa[2] = __float_as_uint(Ps[prow0 + k0 + qd + 4]);
            pa[3] = __float_as_uint(Ps[prow1 + k0 + qd + 4]);
            #pragma unroll
            for (int nt = 0; nt < 8; nt++) {
                int n0 = nt*8;
                uint32_t b0 = __float_as_uint(Vs[(k0+qd  )*VS_STRIDE + n0 + gq]);
                uint32_t b1 = __float_as_uint(Vs[(k0+qd+4)*VS_STRIDE + n0 + gq]);
                mma_tf32(o[nt], pa, b0, b1);
            }
        }
        __syncthreads();   // all warps done with Ks/Vs before next tile load
    }

    // ---- finalize
    float inv0 = 1.f / l0, inv1 = 1.f / l1;
    size_t ob0 = (size_t)(b*SEQ + i0)*VP + h*HD;
    size_t ob1 = (size_t)(b*SEQ + i1)*VP + h*HD;
    #pragma unroll
    for (int nt = 0; nt < 8; nt++) {
        int cl = nt*8 + 2*qd;
        *(float2*)&g_cat[ob0 + cl] = make_float2(o[nt][0]*inv0, o[nt][1]*inv0);
        *(float2*)&g_cat[ob1 + cl] = make_float2(o[nt][2]*inv1, o[nt][3]*inv1);
    }
}

// ---------------- launch ----------------
extern "C" void kernel_launch(void* const* d_in, const int* in_sizes, int n_in,
                              void* d_out, int out_size)
{
    (void)in_sizes; (void)n_in; (void)out_size;
    const float* x     = (const float*)d_in[0];
    const float* gamma = (const float*)d_in[1];
    const float* beta  = (const float*)d_in[2];
    const float* w_in  = (const float*)d_in[3];
    const float* w_out = (const float*)d_in[4];
    const float* b_out = (const float*)d_in[5];
    float* out = (float*)d_out;

    float *p_xt, *p_proj, *p_cat;
    cudaGetSymbolAddress((void**)&p_xt,   g_xt);
    cudaGetSymbolAddress((void**)&p_proj, g_proj);
    cudaGetSymbolAddress((void**)&p_cat,  g_cat);

    ln_kernel<<<ROWS, 128>>>(x, gamma, beta);
    feat_kernel<<<(ROWS*HIDDEN + 255)/256, 256>>>();
    scan_kernel<<<BATCH*64, 256>>>();

    dim3 g1(QKVP/128, ROWS/128);     // (28, 32)
    sgemm_kernel<<<g1, 256>>>(p_xt, w_in, p_proj, nullptr, HIDDEN, HIDDEN, QKVP, QKVP);

    gelu_kernel<<<(ROWS*2048 + 255)/256, 256>>>();

    int attn_smem = (64*KS_STRIDE + 64*VS_STRIDE + 64*KS_STRIDE) * sizeof(float); // 53248
    cudaFuncSetAttribute(attn_mma_kernel, cudaFuncAttributeMaxDynamicSharedMemorySize, attn_smem);
    attn_mma_kernel<<<dim3(SEQ/64, HEADS, BATCH), 128, attn_smem>>>();

    dim3 g2(HIDDEN/128, ROWS/128);   // (4, 32)
    sgemm_kernel<<<g2, 256>>>(p_cat, w_out, out, b_out, VP, VP, HIDDEN, HIDDEN);
}

// round 3
// speedup vs baseline: 5.0116x; 2.4916x over previous
#include <cuda_runtime.h>
#include <math.h>
#include <stdint.h>

#define BATCH  2
#define SEQ    2048
#define ROWS   (BATCH*SEQ)     // 4096
#define HIDDEN 512
#define QKVP   3584            // HIDDEN*(3+EXP)
#define VP     2560            // HIDDEN*(1+EXP)
#define HEADS  8
#define HD     64

// ---------------- scratch (no cudaMalloc allowed) ----------------
__device__ float g_xn[(size_t)ROWS*HIDDEN];          //  8 MB
__device__ float g_xt[(size_t)ROWS*HIDDEN];          //  8 MB
__device__ float g_proj[(size_t)ROWS*QKVP];          // 58.7 MB
__device__ float g_cat[(size_t)ROWS*VP];             // 41.9 MB

// ---------------- LayerNorm: one block per row ----------------
__global__ void __launch_bounds__(128) ln_kernel(const float* __restrict__ x,
                                                 const float* __restrict__ gamma,
                                                 const float* __restrict__ beta)
{
    int row = blockIdx.x;
    int tid = threadIdx.x;
    const float* xr = x + (size_t)row*HIDDEN;
    float v[4];
    float s = 0.f;
    #pragma unroll
    for (int i = 0; i < 4; i++) { v[i] = xr[tid + i*128]; s += v[i]; }
    __shared__ float red[4];
    #pragma unroll
    for (int o = 16; o > 0; o >>= 1) s += __shfl_xor_sync(0xffffffffu, s, o);
    if ((tid & 31) == 0) red[tid >> 5] = s;
    __syncthreads();
    float mu = (red[0]+red[1]+red[2]+red[3]) * (1.f/HIDDEN);
    float vs = 0.f;
    #pragma unroll
    for (int i = 0; i < 4; i++) { float d = v[i]-mu; vs += d*d; }
    #pragma unroll
    for (int o = 16; o > 0; o >>= 1) vs += __shfl_xor_sync(0xffffffffu, vs, o);
    __syncthreads();
    if ((tid & 31) == 0) red[tid >> 5] = vs;
    __syncthreads();
    float var  = (red[0]+red[1]+red[2]+red[3]) * (1.f/HIDDEN);
    float rstd = rsqrtf(var + 1e-5f);
    #pragma unroll
    for (int i = 0; i < 4; i++) {
        int c = tid + i*128;
        g_xn[(size_t)row*HIDDEN + c] = (v[i]-mu)*rstd*gamma[c] + beta[c];
    }
}

// ---------------- feature transform: ident + shifts ----------------
__global__ void feat_kernel()
{
    int idx = blockIdx.x*256 + threadIdx.x;
    if (idx >= ROWS*HIDDEN) return;
    int c   = idx & 511;
    int row = idx >> 9;
    int i   = row & (SEQ-1);
    float val;
    if (c < 320)       val = g_xn[idx];
    else if (c < 384)  return;
    else if (c < 448)  val = (i >= 1) ? g_xn[idx -   HIDDEN] : 0.f;
    else               val = (i >= 2) ? g_xn[idx - 2*HIDDEN] : 0.f;
    g_xt[idx] = val;
}

// ---------------- cumlogsumexp scan: block per (batch, channel) ----------------
__global__ void __launch_bounds__(256) scan_kernel()
{
    int bc  = blockIdx.x;
    int b   = bc >> 6;
    int ch  = 320 + (bc & 63);
    int tid = threadIdx.x;
    int row0 = b*SEQ + tid*8;
    float y[8];
    #pragma unroll
    for (int i = 0; i < 8; i++) y[i] = 5.f * g_xn[(size_t)(row0+i)*HIDDEN + ch];
    float m = -INFINITY, s = 0.f;
    #pragma unroll
    for (int i = 0; i < 8; i++) {
        float M = fmaxf(m, y[i]);
        s = s*expf(m - M) + expf(y[i] - M);
        m = M;
    }
    __shared__ float sm[256], ss[256];
    sm[tid] = m; ss[tid] = s;
    __syncthreads();
    for (int off = 1; off < 256; off <<= 1) {
        float pm = 0.f, ps = 0.f;
        bool act = (tid >= off);
        if (act) { pm = sm[tid-off]; ps = ss[tid-off]; }
        __syncthreads();
        if (act) {
            float M = fmaxf(pm, m);
            s = ps*expf(pm - M) + s*expf(m - M);
            m = M;
            sm[tid] = m; ss[tid] = s;
        }
        __syncthreads();
    }
    float pm = -INFINITY, ps = 0.f;
    if (tid > 0) { pm = sm[tid-1]; ps = ss[tid-1]; }
    #pragma unroll
    for (int i = 0; i < 8; i++) {
        float M = fmaxf(pm, y[i]);
        ps = ps*expf(pm - M) + expf(y[i] - M);
        pm = M;
        g_xt[(size_t)(row0+i)*HIDDEN + ch] = (pm + logf(ps)) * 0.2f;
    }
}

// ---------------- tf32 helpers ----------------
__device__ __forceinline__ float f2tf32(float x) {
    uint32_t r;
    asm("cvt.rna.tf32.f32 %0, %1;" : "=r"(r) : "f"(x));
    return __uint_as_float(r);
}
__device__ __forceinline__ void mma_tf32(float* d, const uint32_t* a, uint32_t b0, uint32_t b1) {
    asm volatile("mma.sync.aligned.m16n8k8.row.col.f32.tf32.tf32.f32 "
        "{%0,%1,%2,%3}, {%4,%5,%6,%7}, {%8,%9}, {%0,%1,%2,%3};"
        : "+f"(d[0]), "+f"(d[1]), "+f"(d[2]), "+f"(d[3])
        : "r"(a[0]), "r"(a[1]), "r"(a[2]), "r"(a[3]), "r"(b0), "r"(b1));
}

// ---------------- tf32 tensor GEMM: C[M,N] = A[M,K] @ B[K,N] (+bias) -----------
// 128x128 block tile, BK=32, 256 thr = 8 warps, warp tile 32x64, double-buffered
#define AS_STRIDE 36    // = 4 (mod 32): a-frag banks gq*4+qd all distinct
#define BS_STRIDE 136   // = 8 (mod 32): b-frag banks qd*8+gq all distinct
__global__ void __launch_bounds__(256) tgemm_kernel(
    const float* __restrict__ A, const float* __restrict__ B,
    float* __restrict__ C, const float* __restrict__ bias,
    int M, int N, int K)
{
    extern __shared__ float smbuf[];
    float* As = smbuf;                           // 2 x 128 x AS_STRIDE
    float* Bs = smbuf + 2*128*AS_STRIDE;         // 2 x 32  x BS_STRIDE

    const int tid  = threadIdx.x;
    const int warp = tid >> 5;
    const int lane = tid & 31;
    const int gq = lane >> 2;
    const int qd = lane & 3;
    const int warp_m = (warp & 3) * 32;          // 4 warps along M
    const int warp_n = (warp >> 2) * 64;         // 2 warps along N
    const int m0 = blockIdx.y * 128;
    const int n0 = blockIdx.x * 128;

    // global load mapping
    const int a_r = tid >> 3;                    // 0..31 (4 passes of +32)
    const int a_c = (tid & 7) << 2;              // 0..28
    const int b_r = tid >> 5;                    // 0..7  (4 passes of +8)
    const int b_c = (tid & 31) << 2;             // 0..124

    const float* Ap = A + (size_t)(m0 + a_r)*K + a_c;
    const float* Bp = B + (size_t)b_r*N + n0 + b_c;

    float acc[2][8][4];
    #pragma unroll
    for (int mt = 0; mt < 2; mt++)
        #pragma unroll
        for (int nt = 0; nt < 8; nt++)
            #pragma unroll
            for (int i = 0; i < 4; i++) acc[mt][nt][i] = 0.f;

    float4 av[4], bv[4];
    // prologue: load tile 0
    #pragma unroll
    for (int i = 0; i < 4; i++) av[i] = *(const float4*)(Ap + (size_t)i*32*K);
    #pragma unroll
    for (int i = 0; i < 4; i++) bv[i] = *(const float4*)(Bp + (size_t)i*8*N);

    const int kTiles = K >> 5;
    int stage = 0;
    {   // store stage 0
        #pragma unroll
        for (int i = 0; i < 4; i++) {
            float* d = &As[(a_r + i*32)*AS_STRIDE + a_c];
            d[0]=f2tf32(av[i].x); d[1]=f2tf32(av[i].y); d[2]=f2tf32(av[i].z); d[3]=f2tf32(av[i].w);
            float4 t = make_float4(f2tf32(bv[i].x), f2tf32(bv[i].y), f2tf32(bv[i].z), f2tf32(bv[i].w));
            *(float4*)&Bs[(b_r + i*8)*BS_STRIDE + b_c] = t;
        }
    }
    __syncthreads();

    for (int t = 0; t < kTiles; t++) {
        // prefetch next tile into regs
        if (t + 1 < kTiles) {
            const float* Ap2 = Ap + (size_t)(t+1)*32;
            const float* Bp2 = Bp + (size_t)(t+1)*32*N;
            #pragma unroll
            for (int i = 0; i < 4; i++) av[i] = *(const float4*)(Ap2 + (size_t)i*32*K);
            #pragma unroll
            for (int i = 0; i < 4; i++) bv[i] = *(const float4*)(Bp2 + (size_t)i*8*N);
        }
        const float* Acur = As + stage*128*AS_STRIDE;
        const float* Bcur = Bs + stage*32*BS_STRIDE;
        #pragma unroll
        for (int kk = 0; kk < 4; kk++) {
            const int k = kk*8;
            uint32_t af[2][4];
            #pragma unroll
            for (int mt = 0; mt < 2; mt++) {
                const int r0 = warp_m + mt*16 + gq;
                af[mt][0] = __float_as_uint(Acur[ r0    *AS_STRIDE + k + qd    ]);
                af[mt][1] = __float_as_uint(Acur[(r0+8) *AS_STRIDE + k + qd    ]);
                af[mt][2] = __float_as_uint(Acur[ r0    *AS_STRIDE + k + qd + 4]);
                af[mt][3] = __float_as_uint(Acur[(r0+8) *AS_STRIDE + k + qd + 4]);
            }
            #pragma unroll
            for (int nt = 0; nt < 8; nt++) {
                const int c = warp_n + nt*8 + gq;
                uint32_t b0 = __float_as_uint(Bcur[(k + qd    )*BS_STRIDE + c]);
                uint32_t b1 = __float_as_uint(Bcur[(k + qd + 4)*BS_STRIDE + c]);
                mma_tf32(acc[0][nt], af[0], b0, b1);
                mma_tf32(acc[1][nt], af[1], b0, b1);
            }
        }
        if (t + 1 < kTiles) {
            stage ^= 1;
            float* Anx = As + stage*128*AS_STRIDE;
            float* Bnx = Bs + stage*32*BS_STRIDE;
            #pragma unroll
            for (int i = 0; i < 4; i++) {
                float* d = &Anx[(a_r + i*32)*AS_STRIDE + a_c];
                d[0]=f2tf32(av[i].x); d[1]=f2tf32(av[i].y); d[2]=f2tf32(av[i].z); d[3]=f2tf32(av[i].w);
                float4 tv = make_float4(f2tf32(bv[i].x), f2tf32(bv[i].y), f2tf32(bv[i].z), f2tf32(bv[i].w));
                *(float4*)&Bnx[(b_r + i*8)*BS_STRIDE + b_c] = tv;
            }
            __syncthreads();
        }
    }

    // epilogue
    #pragma unroll
    for (int mt = 0; mt < 2; mt++) {
        const int r0 = m0 + warp_m + mt*16 + gq;
        #pragma unroll
        for (int nt = 0; nt < 8; nt++) {
            const int c = n0 + warp_n + nt*8 + 2*qd;
            float bx = 0.f, by = 0.f;
            if (bias) { bx = bias[c]; by = bias[c+1]; }
            *(float2*)&C[(size_t)r0    *N + c] = make_float2(acc[mt][nt][0]+bx, acc[mt][nt][1]+by);
            *(float2*)&C[(size_t)(r0+8)*N + c] = make_float2(acc[mt][nt][2]+bx, acc[mt][nt][3]+by);
        }
    }
}

// ---------------- exact GELU on the P slice -> g_cat[:,512:] ----------------
__global__ void gelu_kernel()
{
    int idx = blockIdx.x*256 + threadIdx.x;
    if (idx >= ROWS*2048) return;
    int row = idx >> 11;
    int c   = idx & 2047;
    float xv = g_proj[(size_t)row*QKVP + 1536 + c];
    g_cat[(size_t)row*VP + 512 + c] = 0.5f*xv*(1.f + erff(xv*0.70710678118654752f));
}

// ---------------- flash attention, tf32 mma.sync, Bq=64 Bc=64 ----------------
#define KS_STRIDE 68
#define VS_STRIDE 72
__global__ void __launch_bounds__(128) attn_mma_kernel()
{
    extern __shared__ float smem[];
    float* Ks = smem;
    float* Vs = smem + 64*KS_STRIDE;
    float* Ps = Vs + 64*VS_STRIDE;

    const int qb = blockIdx.x;
    const int h  = blockIdx.y;
    const int b  = blockIdx.z;
    const int q0 = qb*64;
    const int tid  = threadIdx.x;
    const int warp = tid >> 5;
    const int lane = tid & 31;
    const int gq = lane >> 2;
    const int qd = lane & 3;

    const float scale = 0.125f;
    const float slope = exp2f(-(float)(h+1));

    for (int idx = tid; idx < 64*16; idx += 128) {
        int rr = idx >> 4, d4 = (idx & 15) << 2;
        float4 v = *(const float4*)&g_proj[(size_t)(b*SEQ + q0 + rr)*QKVP + h*HD + d4];
        float* dst = &Ks[rr*KS_STRIDE + d4];
        dst[0] = f2tf32(v.x); dst[1] = f2tf32(v.y);
        dst[2] = f2tf32(v.z); dst[3] = f2tf32(v.w);
    }
    __syncthreads();

    uint32_t qf[8][4];
    {
        int r0 = warp*16 + gq;
        #pragma unroll
        for (int kt = 0; kt < 8; kt++) {
            int k0 = kt*8;
            qf[kt][0] = __float_as_uint(Ks[ r0     *KS_STRIDE + k0 + qd    ]);
            qf[kt][1] = __float_as_uint(Ks[(r0+8)  *KS_STRIDE + k0 + qd    ]);
            qf[kt][2] = __float_as_uint(Ks[ r0     *KS_STRIDE + k0 + qd + 4]);
            qf[kt][3] = __float_as_uint(Ks[(r0+8)  *KS_STRIDE + k0 + qd + 4]);
        }
    }
    __syncthreads();

    float o[8][4];
    #pragma unroll
    for (int t = 0; t < 8; t++) { o[t][0]=0.f; o[t][1]=0.f; o[t][2]=0.f; o[t][3]=0.f; }
    float m0 = -INFINITY, m1 = -INFINITY, l0 = 0.f, l1 = 0.f;
    const int i0 = q0 + warp*16 + gq;
    const int i1 = i0 + 8;
    const int prow0 = (warp*16 + gq)*KS_STRIDE;
    const int prow1 = (warp*16 + gq + 8)*KS_STRIDE;

    const int ntiles = qb + 1;
    for (int jt = 0; jt < ntiles; jt++) {
        const int j0 = jt*64;
        for (int idx = tid; idx < 64*16; idx += 128) {
            int rr = idx >> 4, d4 = (idx & 15) << 2;
            size_t base = (size_t)(b*SEQ + j0 + rr)*QKVP + h*HD + d4;
            float4 kv = *(const float4*)&g_proj[base + 512];
            float4 vv = *(const float4*)&g_proj[base + 1024];
            float* kd = &Ks[rr*KS_STRIDE + d4];
            kd[0]=f2tf32(kv.x); kd[1]=f2tf32(kv.y); kd[2]=f2tf32(kv.z); kd[3]=f2tf32(kv.w);
            float* vd = &Vs[rr*VS_STRIDE + d4];
            vd[0]=f2tf32(vv.x); vd[1]=f2tf32(vv.y); vd[2]=f2tf32(vv.z); vd[3]=f2tf32(vv.w);
        }
        __syncthreads();

        float s[8][4];
        #pragma unroll
        for (int t = 0; t < 8; t++) { s[t][0]=0.f; s[t][1]=0.f; s[t][2]=0.f; s[t][3]=0.f; }
        #pragma unroll
        for (int kt = 0; kt < 8; kt++) {
            int k0 = kt*8;
            #pragma unroll
            for (int nt = 0; nt < 8; nt++) {
                int n0 = nt*8;
                uint32_t b0 = __float_as_uint(Ks[(n0+gq)*KS_STRIDE + k0 + qd    ]);
                uint32_t b1 = __float_as_uint(Ks[(n0+gq)*KS_STRIDE + k0 + qd + 4]);
                mma_tf32(s[nt], qf[kt], b0, b1);
            }
        }

        float rm0 = -INFINITY, rm1 = -INFINITY;
        #pragma unroll
        for (int nt = 0; nt < 8; nt++) {
            int j = j0 + nt*8 + 2*qd;
            s[nt][0] = (j   <= i0) ? fmaf(s[nt][0], scale, slope*(float)j    ) : -1e30f;
            s[nt][1] = (j+1 <= i0) ? fmaf(s[nt][1], scale, slope*(float)(j+1)) : -1e30f;
            s[nt][2] = (j   <= i1) ? fmaf(s[nt][2], scale, slope*(float)j    ) : -1e30f;
            s[nt][3] = (j+1 <= i1) ? fmaf(s[nt][3], scale, slope*(float)(j+1)) : -1e30f;
            rm0 = fmaxf(rm0, fmaxf(s[nt][0], s[nt][1]));
            rm1 = fmaxf(rm1, fmaxf(s[nt][2], s[nt][3]));
        }
        rm0 = fmaxf(rm0, __shfl_xor_sync(0xffffffffu, rm0, 1));
        rm0 = fmaxf(rm0, __shfl_xor_sync(0xffffffffu, rm0, 2));
        rm1 = fmaxf(rm1, __shfl_xor_sync(0xffffffffu, rm1, 1));
        rm1 = fmaxf(rm1, __shfl_xor_sync(0xffffffffu, rm1, 2));
        float nm0 = fmaxf(m0, rm0), nm1 = fmaxf(m1, rm1);
        float c0 = __expf(m0 - nm0), c1 = __expf(m1 - nm1);
        m0 = nm0; m1 = nm1;
        float ps0 = 0.f, ps1 = 0.f;
        #pragma unroll
        for (int nt = 0; nt < 8; nt++) {
            float p0 = __expf(s[nt][0] - nm0);
            float p1 = __expf(s[nt][1] - nm0);
            float p2 = __expf(s[nt][2] - nm1);
            float p3 = __expf(s[nt][3] - nm1);
            ps0 += p0 + p1;  ps1 += p2 + p3;
            int cl = nt*8 + 2*qd;
            *(float2*)&Ps[prow0 + cl] = make_float2(f2tf32(p0), f2tf32(p1));
            *(float2*)&Ps[prow1 + cl] = make_float2(f2tf32(p2), f2tf32(p3));
            o[nt][0] *= c0; o[nt][1] *= c0; o[nt][2] *= c1; o[nt][3] *= c1;
        }
        ps0 += __shfl_xor_sync(0xffffffffu, ps0, 1);
        ps0 += __shfl_xor_sync(0xffffffffu, ps0, 2);
        ps1 += __shfl_xor_sync(0xffffffffu, ps1, 1);
        ps1 += __shfl_xor_sync(0xffffffffu, ps1, 2);
        l0 = l0*c0 + ps0;
        l1 = l1*c1 + ps1;
        __syncwarp();

        #pragma unroll
        for (int kt = 0; kt < 8; kt++) {
            int k0 = kt*8;
            uint32_t pa[4];
            pa[0] = __float_as_uint(Ps[prow0 + k0 + qd    ]);
            pa[1] = __float_as_uint(Ps[prow1 + k0 + qd    ]);
            pa[2] = __float_as_uint(Ps[prow0 + k0 + qd + 4]);
            pa[3] = __float_as_uint(Ps[prow1 + k0 + qd + 4]);
            #pragma unroll
            for (int nt = 0; nt < 8; nt++) {
                int n0 = nt*8;
                uint32_t b0 = __float_as_uint(Vs[(k0+qd  )*VS_STRIDE + n0 + gq]);
                uint32_t b1 = __float_as_uint(Vs[(k0+qd+4)*VS_STRIDE + n0 + gq]);
                mma_tf32(o[nt], pa, b0, b1);
            }
        }
        __syncthreads();
    }

    float inv0 = 1.f / l0, inv1 = 1.f / l1;
    size_t ob0 = (size_t)(b*SEQ + i0)*VP + h*HD;
    size_t ob1 = (size_t)(b*SEQ + i1)*VP + h*HD;
    #pragma unroll
    for (int nt = 0; nt < 8; nt++) {
        int cl = nt*8 + 2*qd;
        *(float2*)&g_cat[ob0 + cl] = make_float2(o[nt][0]*inv0, o[nt][1]*inv0);
        *(float2*)&g_cat[ob1 + cl] = make_float2(o[nt][2]*inv1, o[nt][3]*inv1);
    }
}

// ---------------- launch ----------------
extern "C" void kernel_launch(void* const* d_in, const int* in_sizes, int n_in,
                              void* d_out, int out_size)
{
    (void)in_sizes; (void)n_in; (void)out_size;
    const float* x     = (const float*)d_in[0];
    const float* gamma = (const float*)d_in[1];
    const float* beta  = (const float*)d_in[2];
    const float* w_in  = (const float*)d_in[3];
    const float* w_out = (const float*)d_in[4];
    const float* b_out = (const float*)d_in[5];
    float* out = (float*)d_out;

    float *p_xt, *p_proj, *p_cat;
    cudaGetSymbolAddress((void**)&p_xt,   g_xt);
    cudaGetSymbolAddress((void**)&p_proj, g_proj);
    cudaGetSymbolAddress((void**)&p_cat,  g_cat);

    ln_kernel<<<ROWS, 128>>>(x, gamma, beta);
    feat_kernel<<<(ROWS*HIDDEN + 255)/256, 256>>>();
    scan_kernel<<<BATCH*64, 256>>>();

    int gemm_smem = (2*128*AS_STRIDE + 2*32*BS_STRIDE) * sizeof(float);   // 71680
    cudaFuncSetAttribute(tgemm_kernel, cudaFuncAttributeMaxDynamicSharedMemorySize, gemm_smem);

    dim3 g1(QKVP/128, ROWS/128);     // (28, 32)
    tgemm_kernel<<<g1, 256, gemm_smem>>>(p_xt, w_in, p_proj, nullptr, ROWS, QKVP, HIDDEN);

    gelu_kernel<<<(ROWS*2048 + 255)/256, 256>>>();

    int attn_smem = (64*KS_STRIDE + 64*VS_STRIDE + 64*KS_STRIDE) * sizeof(float); // 53248
    cudaFuncSetAttribute(attn_mma_kernel, cudaFuncAttributeMaxDynamicSharedMemorySize, attn_smem);
    attn_mma_kernel<<<dim3(SEQ/64, HEADS, BATCH), 128, attn_smem>>>();

    dim3 g2(HIDDEN/128, ROWS/128);   // (4, 32)
    tgemm_kernel<<<g2, 256, gemm_smem>>>(p_cat, w_out, out, b_out, ROWS, HIDDEN, VP);
}

// round 4
// speedup vs baseline: 5.6028x; 1.1180x over previous
#include <cuda_runtime.h>
#include <math.h>
#include <stdint.h>

#define BATCH  2
#define SEQ    2048
#define ROWS   (BATCH*SEQ)     // 4096
#define HIDDEN 512
#define QKVP   3584            // HIDDEN*(3+EXP)
#define VP     2560            // HIDDEN*(1+EXP)
#define HEADS  8
#define HD     64

// ---------------- scratch (no cudaMalloc allowed) ----------------
__device__ float g_xn[(size_t)ROWS*HIDDEN];          //  8 MB
__device__ float g_xt[(size_t)ROWS*HIDDEN];          //  8 MB   (tf32-rounded)
__device__ float g_proj[(size_t)ROWS*QKVP];          // 58.7 MB (fp32)
__device__ float g_cat[(size_t)ROWS*VP];             // 41.9 MB (tf32-rounded)
__device__ float g_w1[(size_t)HIDDEN*QKVP];          //  7.3 MB (tf32 w_in)
__device__ float g_w2[(size_t)VP*HIDDEN];            //  5.2 MB (tf32 w_out)

// ---------------- tf32 helpers ----------------
__device__ __forceinline__ float f2tf32(float x) {
    uint32_t r;
    asm("cvt.rna.tf32.f32 %0, %1;" : "=r"(r) : "f"(x));
    return __uint_as_float(r);
}
__device__ __forceinline__ void mma_tf32(float* d, const uint32_t* a, uint32_t b0, uint32_t b1) {
    asm volatile("mma.sync.aligned.m16n8k8.row.col.f32.tf32.tf32.f32 "
        "{%0,%1,%2,%3}, {%4,%5,%6,%7}, {%8,%9}, {%0,%1,%2,%3};"
        : "+f"(d[0]), "+f"(d[1]), "+f"(d[2]), "+f"(d[3])
        : "r"(a[0]), "r"(a[1]), "r"(a[2]), "r"(a[3]), "r"(b0), "r"(b1));
}
__device__ __forceinline__ void cp16(uint32_t dst, const void* src) {
    asm volatile("cp.async.cg.shared.global [%0], [%1], 16;" :: "r"(dst), "l"(src));
}

// ---------------- weight pre-round to tf32 ----------------
__global__ void cvt_kernel(const float* __restrict__ src, float* __restrict__ dst, int n)
{
    int i = blockIdx.x*256 + threadIdx.x;
    if (i*4 >= n) return;
    float4 v = *(const float4*)&src[i*4];
    float4 o = make_float4(f2tf32(v.x), f2tf32(v.y), f2tf32(v.z), f2tf32(v.w));
    *(float4*)&dst[i*4] = o;
}

// ---------------- LayerNorm: one block per row ----------------
__global__ void __launch_bounds__(128) ln_kernel(const float* __restrict__ x,
                                                 const float* __restrict__ gamma,
                                                 const float* __restrict__ beta)
{
    int row = blockIdx.x;
    int tid = threadIdx.x;
    const float* xr = x + (size_t)row*HIDDEN;
    float v[4];
    float s = 0.f;
    #pragma unroll
    for (int i = 0; i < 4; i++) { v[i] = xr[tid + i*128]; s += v[i]; }
    __shared__ float red[4];
    #pragma unroll
    for (int o = 16; o > 0; o >>= 1) s += __shfl_xor_sync(0xffffffffu, s, o);
    if ((tid & 31) == 0) red[tid >> 5] = s;
    __syncthreads();
    float mu = (red[0]+red[1]+red[2]+red[3]) * (1.f/HIDDEN);
    float vs = 0.f;
    #pragma unroll
    for (int i = 0; i < 4; i++) { float d = v[i]-mu; vs += d*d; }
    #pragma unroll
    for (int o = 16; o > 0; o >>= 1) vs += __shfl_xor_sync(0xffffffffu, vs, o);
    __syncthreads();
    if ((tid & 31) == 0) red[tid >> 5] = vs;
    __syncthreads();
    float var  = (red[0]+red[1]+red[2]+red[3]) * (1.f/HIDDEN);
    float rstd = rsqrtf(var + 1e-5f);
    #pragma unroll
    for (int i = 0; i < 4; i++) {
        int c = tid + i*128;
        g_xn[(size_t)row*HIDDEN + c] = (v[i]-mu)*rstd*gamma[c] + beta[c];
    }
}

// ---------------- feature transform: ident + shifts (tf32-rounded out) --------
__global__ void feat_kernel()
{
    int idx = blockIdx.x*256 + threadIdx.x;
    if (idx >= ROWS*HIDDEN) return;
    int c   = idx & 511;
    int row = idx >> 9;
    int i   = row & (SEQ-1);
    float val;
    if (c < 320)       val = g_xn[idx];
    else if (c < 384)  return;
    else if (c < 448)  val = (i >= 1) ? g_xn[idx -   HIDDEN] : 0.f;
    else               val = (i >= 2) ? g_xn[idx - 2*HIDDEN] : 0.f;
    g_xt[idx] = f2tf32(val);
}

// ---------------- cumlogsumexp scan (tf32-rounded out) ----------------
__global__ void __launch_bounds__(256) scan_kernel()
{
    int bc  = blockIdx.x;
    int b   = bc >> 6;
    int ch  = 320 + (bc & 63);
    int tid = threadIdx.x;
    int row0 = b*SEQ + tid*8;
    float y[8];
    #pragma unroll
    for (int i = 0; i < 8; i++) y[i] = 5.f * g_xn[(size_t)(row0+i)*HIDDEN + ch];
    float m = -INFINITY, s = 0.f;
    #pragma unroll
    for (int i = 0; i < 8; i++) {
        float M = fmaxf(m, y[i]);
        s = s*expf(m - M) + expf(y[i] - M);
        m = M;
    }
    __shared__ float sm[256], ss[256];
    sm[tid] = m; ss[tid] = s;
    __syncthreads();
    for (int off = 1; off < 256; off <<= 1) {
        float pm = 0.f, ps = 0.f;
        bool act = (tid >= off);
        if (act) { pm = sm[tid-off]; ps = ss[tid-off]; }
        __syncthreads();
        if (act) {
            float M = fmaxf(pm, m);
            s = ps*expf(pm - M) + s*expf(m - M);
            m = M;
            sm[tid] = m; ss[tid] = s;
        }
        __syncthreads();
    }
    float pm = -INFINITY, ps = 0.f;
    if (tid > 0) { pm = sm[tid-1]; ps = ss[tid-1]; }
    #pragma unroll
    for (int i = 0; i < 8; i++) {
        float M = fmaxf(pm, y[i]);
        ps = ps*expf(pm - M) + expf(y[i] - M);
        pm = M;
        g_xt[(size_t)(row0+i)*HIDDEN + ch] = f2tf32((pm + logf(ps)) * 0.2f);
    }
}

// ---------------- tf32 tensor GEMM w/ cp.async, 2-stage, 2 CTA/SM -------------
// inputs A,B must already be tf32-rounded
#define AS_STRIDE 36    // = 4 (mod 32)
#define BS_STRIDE 136   // = 8 (mod 32)
#define A_STG_BYTES (128*AS_STRIDE*4)
#define B_STG_BYTES (32*BS_STRIDE*4)
__global__ void __launch_bounds__(256, 2) tgemm_kernel(
    const float* __restrict__ A, const float* __restrict__ B,
    float* __restrict__ C, const float* __restrict__ bias,
    int M, int N, int K)
{
    extern __shared__ float smbuf[];
    float* As = smbuf;                           // 2 x 128 x AS_STRIDE
    float* Bs = smbuf + 2*128*AS_STRIDE;         // 2 x 32  x BS_STRIDE

    const int tid  = threadIdx.x;
    const int warp = tid >> 5;
    const int lane = tid & 31;
    const int gq = lane >> 2;
    const int qd = lane & 3;
    const int warp_m = (warp & 3) * 32;
    const int warp_n = (warp >> 2) * 64;
    const int m0 = blockIdx.y * 128;
    const int n0 = blockIdx.x * 128;

    const int a_r = tid >> 3;
    const int a_c = (tid & 7) << 2;
    const int b_r = tid >> 5;
    const int b_c = (tid & 31) << 2;

    const uint32_t as_u = (uint32_t)__cvta_generic_to_shared(As);
    const uint32_t bs_u = (uint32_t)__cvta_generic_to_shared(Bs);
    const uint32_t a_dst0 = as_u + ((uint32_t)(a_r*AS_STRIDE + a_c) << 2);
    const uint32_t b_dst0 = bs_u + ((uint32_t)(b_r*BS_STRIDE + b_c) << 2);

    const float* Ag0 = A + (size_t)(m0 + a_r)*K + a_c;
    const float* Bg0 = B + (size_t)b_r*N + n0 + b_c;

    const int kTiles = K >> 5;

    // prologue: issue stage 0 and stage 1
    #pragma unroll
    for (int s = 0; s < 2; s++) {
        if (s < kTiles) {
            const float* Ag = Ag0 + s*32;
            const float* Bg = Bg0 + (size_t)s*32*N;
            #pragma unroll
            for (int i = 0; i < 4; i++)
                cp16(a_dst0 + s*A_STG_BYTES + i*32*AS_STRIDE*4, Ag + (size_t)i*32*K);
            #pragma unroll
            for (int i = 0; i < 4; i++)
                cp16(b_dst0 + s*B_STG_BYTES + i*8*BS_STRIDE*4, Bg + (size_t)i*8*N);
        }
        asm volatile("cp.async.commit_group;");
    }
    asm volatile("cp.async.wait_group 1;");
    __syncthreads();

    float acc[2][8][4];
    #pragma unroll
    for (int mt = 0; mt < 2; mt++)
        #pragma unroll
        for (int nt = 0; nt < 8; nt++)
            #pragma unroll
            for (int i = 0; i < 4; i++) acc[mt][nt][i] = 0.f;

    for (int t = 0; t < kTiles; t++) {
        const int stage = t & 1;
        const float* Acur = As + stage*128*AS_STRIDE;
        const float* Bcur = Bs + stage*32*BS_STRIDE;
        #pragma unroll
        for (int kk = 0; kk < 4; kk++) {
            const int k = kk*8;
            uint32_t af[2][4];
            #pragma unroll
            for (int mt = 0; mt < 2; mt++) {
                const int r0 = warp_m + mt*16 + gq;
                af[mt][0] = __float_as_uint(Acur[ r0    *AS_STRIDE + k + qd    ]);
                af[mt][1] = __float_as_uint(Acur[(r0+8) *AS_STRIDE + k + qd    ]);
                af[mt][2] = __float_as_uint(Acur[ r0    *AS_STRIDE + k + qd + 4]);
                af[mt][3] = __float_as_uint(Acur[(r0+8) *AS_STRIDE + k + qd + 4]);
            }
            #pragma unroll
            for (int nt = 0; nt < 8; nt++) {
                const int c = warp_n + nt*8 + gq;
                uint32_t b0 = __float_as_uint(Bcur[(k + qd    )*BS_STRIDE + c]);
                uint32_t b1 = __float_as_uint(Bcur[(k + qd + 4)*BS_STRIDE + c]);
                mma_tf32(acc[0][nt], af[0], b0, b1);
                mma_tf32(acc[1][nt], af[1], b0, b1);
            }
        }
        if (t + 1 < kTiles) {
            __syncthreads();     // everyone done reading this stage
            if (t + 2 < kTiles) {
                const float* Ag = Ag0 + (t+2)*32;
                const float* Bg = Bg0 + (size_t)(t+2)*32*N;
                #pragma unroll
                for (int i = 0; i < 4; i++)
                    cp16(a_dst0 + stage*A_STG_BYTES + i*32*AS_STRIDE*4, Ag + (size_t)i*32*K);
                #pragma unroll
                for (int i = 0; i < 4; i++)
                    cp16(b_dst0 + stage*B_STG_BYTES + i*8*BS_STRIDE*4, Bg + (size_t)i*8*N);
            }
            asm volatile("cp.async.commit_group;");
            asm volatile("cp.async.wait_group 1;");
            __syncthreads();     // next stage ready
        }
    }

    // epilogue
    #pragma unroll
    for (int mt = 0; mt < 2; mt++) {
        const int r0 = m0 + warp_m + mt*16 + gq;
        #pragma unroll
        for (int nt = 0; nt < 8; nt++) {
            const int c = n0 + warp_n + nt*8 + 2*qd;
            float bx = 0.f, by = 0.f;
            if (bias) { bx = bias[c]; by = bias[c+1]; }
            *(float2*)&C[(size_t)r0    *N + c] = make_float2(acc[mt][nt][0]+bx, acc[mt][nt][1]+by);
            *(float2*)&C[(size_t)(r0+8)*N + c] = make_float2(acc[mt][nt][2]+bx, acc[mt][nt][3]+by);
        }
    }
}

// ---------------- exact GELU on the P slice -> g_cat[:,512:] (tf32 out) -------
__global__ void gelu_kernel()
{
    int idx = blockIdx.x*256 + threadIdx.x;
    if (idx >= ROWS*2048) return;
    int row = idx >> 11;
    int c   = idx & 2047;
    float xv = g_proj[(size_t)row*QKVP + 1536 + c];
    g_cat[(size_t)row*VP + 512 + c] = f2tf32(0.5f*xv*(1.f + erff(xv*0.70710678118654752f)));
}

// ---------------- flash attention, tf32 mma.sync, Bq=64 Bc=64 ----------------
#define KS_STRIDE 68
#define VS_STRIDE 72
__global__ void __launch_bounds__(128) attn_mma_kernel()
{
    extern __shared__ float smem[];
    float* Ks = smem;
    float* Vs = smem + 64*KS_STRIDE;
    float* Ps = Vs + 64*VS_STRIDE;

    const int qb = blockIdx.x;
    const int h  = blockIdx.y;
    const int b  = blockIdx.z;
    const int q0 = qb*64;
    const int tid  = threadIdx.x;
    const int warp = tid >> 5;
    const int lane = tid & 31;
    const int gq = lane >> 2;
    const int qd = lane & 3;

    const float scale = 0.125f;
    const float slope = exp2f(-(float)(h+1));

    for (int idx = tid; idx < 64*16; idx += 128) {
        int rr = idx >> 4, d4 = (idx & 15) << 2;
        float4 v = *(const float4*)&g_proj[(size_t)(b*SEQ + q0 + rr)*QKVP + h*HD + d4];
        float* dst = &Ks[rr*KS_STRIDE + d4];
        dst[0] = f2tf32(v.x); dst[1] = f2tf32(v.y);
        dst[2] = f2tf32(v.z); dst[3] = f2tf32(v.w);
    }
    __syncthreads();

    uint32_t qf[8][4];
    {
        int r0 = warp*16 + gq;
        #pragma unroll
        for (int kt = 0; kt < 8; kt++) {
            int k0 = kt*8;
            qf[kt][0] = __float_as_uint(Ks[ r0     *KS_STRIDE + k0 + qd    ]);
            qf[kt][1] = __float_as_uint(Ks[(r0+8)  *KS_STRIDE + k0 + qd    ]);
            qf[kt][2] = __float_as_uint(Ks[ r0     *KS_STRIDE + k0 + qd + 4]);
            qf[kt][3] = __float_as_uint(Ks[(r0+8)  *KS_STRIDE + k0 + qd + 4]);
        }
    }
    __syncthreads();

    float o[8][4];
    #pragma unroll
    for (int t = 0; t < 8; t++) { o[t][0]=0.f; o[t][1]=0.f; o[t][2]=0.f; o[t][3]=0.f; }
    float m0 = -INFINITY, m1 = -INFINITY, l0 = 0.f, l1 = 0.f;
    const int i0 = q0 + warp*16 + gq;
    const int i1 = i0 + 8;
    const int prow0 = (warp*16 + gq)*KS_STRIDE;
    const int prow1 = (warp*16 + gq + 8)*KS_STRIDE;

    const int ntiles = qb + 1;
    for (int jt = 0; jt < ntiles; jt++) {
        const int j0 = jt*64;
        for (int idx = tid; idx < 64*16; idx += 128) {
            int rr = idx >> 4, d4 = (idx & 15) << 2;
            size_t base = (size_t)(b*SEQ + j0 + rr)*QKVP + h*HD + d4;
            float4 kv = *(const float4*)&g_proj[base + 512];
            float4 vv = *(const float4*)&g_proj[base + 1024];
            float* kd = &Ks[rr*KS_STRIDE + d4];
            kd[0]=f2tf32(kv.x); kd[1]=f2tf32(kv.y); kd[2]=f2tf32(kv.z); kd[3]=f2tf32(kv.w);
            float* vd = &Vs[rr*VS_STRIDE + d4];
            vd[0]=f2tf32(vv.x); vd[1]=f2tf32(vv.y); vd[2]=f2tf32(vv.z); vd[3]=f2tf32(vv.w);
        }
        __syncthreads();

        float s[8][4];
        #pragma unroll
        for (int t = 0; t < 8; t++) { s[t][0]=0.f; s[t][1]=0.f; s[t][2]=0.f; s[t][3]=0.f; }
        #pragma unroll
        for (int kt = 0; kt < 8; kt++) {
            int k0 = kt*8;
            #pragma unroll
            for (int nt = 0; nt < 8; nt++) {
                int n0 = nt*8;
                uint32_t b0 = __float_as_uint(Ks[(n0+gq)*KS_STRIDE + k0 + qd    ]);
                uint32_t b1 = __float_as_uint(Ks[(n0+gq)*KS_STRIDE + k0 + qd + 4]);
                mma_tf32(s[nt], qf[kt], b0, b1);
            }
        }

        float rm0 = -INFINITY, rm1 = -INFINITY;
        #pragma unroll
        for (int nt = 0; nt < 8; nt++) {
            int j = j0 + nt*8 + 2*qd;
            s[nt][0] = (j   <= i0) ? fmaf(s[nt][0], scale, slope*(float)j    ) : -1e30f;
            s[nt][1] = (j+1 <= i0) ? fmaf(s[nt][1], scale, slope*(float)(j+1)) : -1e30f;
            s[nt][2] = (j   <= i1) ? fmaf(s[nt][2], scale, slope*(float)j    ) : -1e30f;
            s[nt][3] = (j+1 <= i1) ? fmaf(s[nt][3], scale, slope*(float)(j+1)) : -1e30f;
            rm0 = fmaxf(rm0, fmaxf(s[nt][0], s[nt][1]));
            rm1 = fmaxf(rm1, fmaxf(s[nt][2], s[nt][3]));
        }
        rm0 = fmaxf(rm0, __shfl_xor_sync(0xffffffffu, rm0, 1));
        rm0 = fmaxf(rm0, __shfl_xor_sync(0xffffffffu, rm0, 2));
        rm1 = fmaxf(rm1, __shfl_xor_sync(0xffffffffu, rm1, 1));
        rm1 = fmaxf(rm1, __shfl_xor_sync(0xffffffffu, rm1, 2));
        float nm0 = fmaxf(m0, rm0), nm1 = fmaxf(m1, rm1);
        float c0 = __expf(m0 - nm0), c1 = __expf(m1 - nm1);
        m0 = nm0; m1 = nm1;
        float ps0 = 0.f, ps1 = 0.f;
        #pragma unroll
        for (int nt = 0; nt < 8; nt++) {
            float p0 = __expf(s[nt][0] - nm0);
            float p1 = __expf(s[nt][1] - nm0);
            float p2 = __expf(s[nt][2] - nm1);
            float p3 = __expf(s[nt][3] - nm1);
            ps0 += p0 + p1;  ps1 += p2 + p3;
            int cl = nt*8 + 2*qd;
            *(float2*)&Ps[prow0 + cl] = make_float2(f2tf32(p0), f2tf32(p1));
            *(float2*)&Ps[prow1 + cl] = make_float2(f2tf32(p2), f2tf32(p3));
            o[nt][0] *= c0; o[nt][1] *= c0; o[nt][2] *= c1; o[nt][3] *= c1;
        }
        ps0 += __shfl_xor_sync(0xffffffffu, ps0, 1);
        ps0 += __shfl_xor_sync(0xffffffffu, ps0, 2);
        ps1 += __shfl_xor_sync(0xffffffffu, ps1, 1);
        ps1 += __shfl_xor_sync(0xffffffffu, ps1, 2);
        l0 = l0*c0 + ps0;
        l1 = l1*c1 + ps1;
        __syncwarp();

        #pragma unroll
        for (int kt = 0; kt < 8; kt++) {
            int k0 = kt*8;
            uint32_t pa[4];
            pa[0] = __float_as_uint(Ps[prow0 + k0 + qd    ]);
            pa[1] = __float_as_uint(Ps[prow1 + k0 + qd    ]);
            pa[2] = __float_as_uint(Ps[prow0 + k0 + qd + 4]);
            pa[3] = __float_as_uint(Ps[prow1 + k0 + qd + 4]);
            #pragma unroll
            for (int nt = 0; nt < 8; nt++) {
                int n0 = nt*8;
                uint32_t b0 = __float_as_uint(Vs[(k0+qd  )*VS_STRIDE + n0 + gq]);
                uint32_t b1 = __float_as_uint(Vs[(k0+qd+4)*VS_STRIDE + n0 + gq]);
                mma_tf32(o[nt], pa, b0, b1);
            }
        }
        __syncthreads();
    }

    // finalize (tf32-rounded: feeds tgemm2 A)
    float inv0 = 1.f / l0, inv1 = 1.f / l1;
    size_t ob0 = (size_t)(b*SEQ + i0)*VP + h*HD;
    size_t ob1 = (size_t)(b*SEQ + i1)*VP + h*HD;
    #pragma unroll
    for (int nt = 0; nt < 8; nt++) {
        int cl = nt*8 + 2*qd;
        *(float2*)&g_cat[ob0 + cl] = make_float2(f2tf32(o[nt][0]*inv0), f2tf32(o[nt][1]*inv0));
        *(float2*)&g_cat[ob1 + cl] = make_float2(f2tf32(o[nt][2]*inv1), f2tf32(o[nt][3]*inv1));
    }
}

// ---------------- launch ----------------
extern "C" void kernel_launch(void* const* d_in, const int* in_sizes, int n_in,
                              void* d_out, int out_size)
{
    (void)in_sizes; (void)n_in; (void)out_size;
    const float* x     = (const float*)d_in[0];
    const float* gamma = (const float*)d_in[1];
    const float* beta  = (const float*)d_in[2];
    const float* w_in  = (const float*)d_in[3];
    const float* w_out = (const float*)d_in[4];
    const float* b_out = (const float*)d_in[5];
    float* out = (float*)d_out;

    float *p_xt, *p_cat, *p_proj, *p_w1, *p_w2;
    cudaGetSymbolAddress((void**)&p_xt,   g_xt);
    cudaGetSymbolAddress((void**)&p_proj, g_proj);
    cudaGetSymbolAddress((void**)&p_cat,  g_cat);
    cudaGetSymbolAddress((void**)&p_w1,   g_w1);
    cudaGetSymbolAddress((void**)&p_w2,   g_w2);

    // weight pre-round (cheap, graph-capturable)
    cvt_kernel<<<(HIDDEN*QKVP/4 + 255)/256, 256>>>(w_in,  p_w1, HIDDEN*QKVP);
    cvt_kernel<<<(VP*HIDDEN/4   + 255)/256, 256>>>(w_out, p_w2, VP*HIDDEN);

    ln_kernel<<<ROWS, 128>>>(x, gamma, beta);
    feat_kernel<<<(ROWS*HIDDEN + 255)/256, 256>>>();
    scan_kernel<<<BATCH*64, 256>>>();

    int gemm_smem = (2*128*AS_STRIDE + 2*32*BS_STRIDE) * sizeof(float);   // 71680
    cudaFuncSetAttribute(tgemm_kernel, cudaFuncAttributeMaxDynamicSharedMemorySize, gemm_smem);

    dim3 g1(QKVP/128, ROWS/128);     // (28, 32)
    tgemm_kernel<<<g1, 256, gemm_smem>>>(p_xt, p_w1, p_proj, nullptr, ROWS, QKVP, HIDDEN);

    gelu_kernel<<<(ROWS*2048 + 255)/256, 256>>>();

    int attn_smem = (64*KS_STRIDE + 64*VS_STRIDE + 64*KS_STRIDE) * sizeof(float); // 53248
    cudaFuncSetAttribute(attn_mma_kernel, cudaFuncAttributeMaxDynamicSharedMemorySize, attn_smem);
    attn_mma_kernel<<<dim3(SEQ/64, HEADS, BATCH), 128, attn_smem>>>();

    dim3 g2(HIDDEN/128, ROWS/128);   // (4, 32)
    tgemm_kernel<<<g2, 256, gemm_smem>>>(p_cat, p_w2, out, b_out, ROWS, HIDDEN, VP);
}

// round 5
// speedup vs baseline: 5.7853x; 1.0326x over previous
#include <cuda_runtime.h>
#include <math.h>
#include <stdint.h>

#define BATCH  2
#define SEQ    2048
#define ROWS   (BATCH*SEQ)     // 4096
#define HIDDEN 512
#define QKVP   3584            // HIDDEN*(3+EXP)
#define VP     2560            // HIDDEN*(1+EXP)
#define HEADS  8
#define HD     64

// ---------------- scratch (no cudaMalloc allowed) ----------------
__device__ float g_xn[(size_t)ROWS*HIDDEN];          //  8 MB
__device__ float g_xt[(size_t)ROWS*HIDDEN];          //  8 MB   (tf32-rounded)
__device__ float g_proj[(size_t)ROWS*QKVP];          // q,k,v slices only (tf32-rounded)
__device__ float g_cat[(size_t)ROWS*VP];             // 41.9 MB (tf32-rounded)
__device__ float g_w1[(size_t)HIDDEN*QKVP];          //  7.3 MB (tf32 w_in)
__device__ float g_w2[(size_t)VP*HIDDEN];            //  5.2 MB (tf32 w_out)

// ---------------- tf32 helpers ----------------
__device__ __forceinline__ float f2tf32(float x) {
    uint32_t r;
    asm("cvt.rna.tf32.f32 %0, %1;" : "=r"(r) : "f"(x));
    return __uint_as_float(r);
}
__device__ __forceinline__ void mma_tf32(float* d, const uint32_t* a, uint32_t b0, uint32_t b1) {
    asm volatile("mma.sync.aligned.m16n8k8.row.col.f32.tf32.tf32.f32 "
        "{%0,%1,%2,%3}, {%4,%5,%6,%7}, {%8,%9}, {%0,%1,%2,%3};"
        : "+f"(d[0]), "+f"(d[1]), "+f"(d[2]), "+f"(d[3])
        : "r"(a[0]), "r"(a[1]), "r"(a[2]), "r"(a[3]), "r"(b0), "r"(b1));
}
__device__ __forceinline__ void cp16(uint32_t dst, const void* src) {
    asm volatile("cp.async.cg.shared.global [%0], [%1], 16;" :: "r"(dst), "l"(src));
}

// ---------------- weight pre-round to tf32 ----------------
__global__ void cvt_kernel(const float* __restrict__ src, float* __restrict__ dst, int n)
{
    int i = blockIdx.x*256 + threadIdx.x;
    if (i*4 >= n) return;
    float4 v = *(const float4*)&src[i*4];
    float4 o = make_float4(f2tf32(v.x), f2tf32(v.y), f2tf32(v.z), f2tf32(v.w));
    *(float4*)&dst[i*4] = o;
}

// ---------------- LayerNorm: one block per row ----------------
__global__ void __launch_bounds__(128) ln_kernel(const float* __restrict__ x,
                                                 const float* __restrict__ gamma,
                                                 const float* __restrict__ beta)
{
    int row = blockIdx.x;
    int tid = threadIdx.x;
    const float* xr = x + (size_t)row*HIDDEN;
    float v[4];
    float s = 0.f;
    #pragma unroll
    for (int i = 0; i < 4; i++) { v[i] = xr[tid + i*128]; s += v[i]; }
    __shared__ float red[4];
    #pragma unroll
    for (int o = 16; o > 0; o >>= 1) s += __shfl_xor_sync(0xffffffffu, s, o);
    if ((tid & 31) == 0) red[tid >> 5] = s;
    __syncthreads();
    float mu = (red[0]+red[1]+red[2]+red[3]) * (1.f/HIDDEN);
    float vs = 0.f;
    #pragma unroll
    for (int i = 0; i < 4; i++) { float d = v[i]-mu; vs += d*d; }
    #pragma unroll
    for (int o = 16; o > 0; o >>= 1) vs += __shfl_xor_sync(0xffffffffu, vs, o);
    __syncthreads();
    if ((tid & 31) == 0) red[tid >> 5] = vs;
    __syncthreads();
    float var  = (red[0]+red[1]+red[2]+red[3]) * (1.f/HIDDEN);
    float rstd = rsqrtf(var + 1e-5f);
    #pragma unroll
    for (int i = 0; i < 4; i++) {
        int c = tid + i*128;
        g_xn[(size_t)row*HIDDEN + c] = (v[i]-mu)*rstd*gamma[c] + beta[c];
    }
}

// ---------------- feature transform: ident + shifts (tf32-rounded out) --------
__global__ void feat_kernel()
{
    int idx = blockIdx.x*256 + threadIdx.x;
    if (idx >= ROWS*HIDDEN) return;
    int c   = idx & 511;
    int row = idx >> 9;
    int i   = row & (SEQ-1);
    float val;
    if (c < 320)       val = g_xn[idx];
    else if (c < 384)  return;
    else if (c < 448)  val = (i >= 1) ? g_xn[idx -   HIDDEN] : 0.f;
    else               val = (i >= 2) ? g_xn[idx - 2*HIDDEN] : 0.f;
    g_xt[idx] = f2tf32(val);
}

// ---------------- cumlogsumexp scan (tf32-rounded out) ----------------
__global__ void __launch_bounds__(256) scan_kernel()
{
    int bc  = blockIdx.x;
    int b   = bc >> 6;
    int ch  = 320 + (bc & 63);
    int tid = threadIdx.x;
    int row0 = b*SEQ + tid*8;
    float y[8];
    #pragma unroll
    for (int i = 0; i < 8; i++) y[i] = 5.f * g_xn[(size_t)(row0+i)*HIDDEN + ch];
    float m = -INFINITY, s = 0.f;
    #pragma unroll
    for (int i = 0; i < 8; i++) {
        float M = fmaxf(m, y[i]);
        s = s*expf(m - M) + expf(y[i] - M);
        m = M;
    }
    __shared__ float sm[256], ss[256];
    sm[tid] = m; ss[tid] = s;
    __syncthreads();
    for (int off = 1; off < 256; off <<= 1) {
        float pm = 0.f, ps = 0.f;
        bool act = (tid >= off);
        if (act) { pm = sm[tid-off]; ps = ss[tid-off]; }
        __syncthreads();
        if (act) {
            float M = fmaxf(pm, m);
            s = ps*expf(pm - M) + s*expf(m - M);
            m = M;
            sm[tid] = m; ss[tid] = s;
        }
        __syncthreads();
    }
    float pm = -INFINITY, ps = 0.f;
    if (tid > 0) { pm = sm[tid-1]; ps = ss[tid-1]; }
    #pragma unroll
    for (int i = 0; i < 8; i++) {
        float M = fmaxf(pm, y[i]);
        ps = ps*expf(pm - M) + expf(y[i] - M);
        pm = M;
        g_xt[(size_t)(row0+i)*HIDDEN + ch] = f2tf32((pm + logf(ps)) * 0.2f);
    }
}

// ---------------- tf32 tensor GEMM w/ cp.async, 2-stage ----------------------
// MODE 0: plain fp32 C + bias (final output)
// MODE 1: proj mode — cols < 1536: f2tf32 -> C (g_proj);
//                     cols >= 1536: gelu(acc) -> g_cat[row*VP + c - 1024] (tf32)
#define AS_STRIDE 36    // = 4 (mod 32)
#define BS_STRIDE 136   // = 8 (mod 32)
#define A_STG_BYTES (128*AS_STRIDE*4)
#define B_STG_BYTES (32*BS_STRIDE*4)
template<int MODE>
__global__ void __launch_bounds__(256, 2) tgemm_kernel(
    const float* __restrict__ A, const float* __restrict__ B,
    float* __restrict__ C, const float* __restrict__ bias,
    int M, int N, int K)
{
    extern __shared__ float smbuf[];
    float* As = smbuf;
    float* Bs = smbuf + 2*128*AS_STRIDE;

    const int tid  = threadIdx.x;
    const int warp = tid >> 5;
    const int lane = tid & 31;
    const int gq = lane >> 2;
    const int qd = lane & 3;
    const int warp_m = (warp & 3) * 32;
    const int warp_n = (warp >> 2) * 64;
    const int m0 = blockIdx.y * 128;
    const int n0 = blockIdx.x * 128;

    const int a_r = tid >> 3;
    const int a_c = (tid & 7) << 2;
    const int b_r = tid >> 5;
    const int b_c = (tid & 31) << 2;

    const uint32_t as_u = (uint32_t)__cvta_generic_to_shared(As);
    const uint32_t bs_u = (uint32_t)__cvta_generic_to_shared(Bs);
    const uint32_t a_dst0 = as_u + ((uint32_t)(a_r*AS_STRIDE + a_c) << 2);
    const uint32_t b_dst0 = bs_u + ((uint32_t)(b_r*BS_STRIDE + b_c) << 2);

    const float* Ag0 = A + (size_t)(m0 + a_r)*K + a_c;
    const float* Bg0 = B + (size_t)b_r*N + n0 + b_c;

    const int kTiles = K >> 5;

    #pragma unroll
    for (int s = 0; s < 2; s++) {
        if (s < kTiles) {
            const float* Ag = Ag0 + s*32;
            const float* Bg = Bg0 + (size_t)s*32*N;
            #pragma unroll
            for (int i = 0; i < 4; i++)
                cp16(a_dst0 + s*A_STG_BYTES + i*32*AS_STRIDE*4, Ag + (size_t)i*32*K);
            #pragma unroll
            for (int i = 0; i < 4; i++)
                cp16(b_dst0 + s*B_STG_BYTES + i*8*BS_STRIDE*4, Bg + (size_t)i*8*N);
        }
        asm volatile("cp.async.commit_group;");
    }
    asm volatile("cp.async.wait_group 1;");
    __syncthreads();

    float acc[2][8][4];
    #pragma unroll
    for (int mt = 0; mt < 2; mt++)
        #pragma unroll
        for (int nt = 0; nt < 8; nt++)
            #pragma unroll
            for (int i = 0; i < 4; i++) acc[mt][nt][i] = 0.f;

    for (int t = 0; t < kTiles; t++) {
        const int stage = t & 1;
        const float* Acur = As + stage*128*AS_STRIDE;
        const float* Bcur = Bs + stage*32*BS_STRIDE;
        #pragma unroll
        for (int kk = 0; kk < 4; kk++) {
            const int k = kk*8;
            uint32_t af[2][4];
            #pragma unroll
            for (int mt = 0; mt < 2; mt++) {
                const int r0 = warp_m + mt*16 + gq;
                af[mt][0] = __float_as_uint(Acur[ r0    *AS_STRIDE + k + qd    ]);
                af[mt][1] = __float_as_uint(Acur[(r0+8) *AS_STRIDE + k + qd    ]);
                af[mt][2] = __float_as_uint(Acur[ r0    *AS_STRIDE + k + qd + 4]);
                af[mt][3] = __float_as_uint(Acur[(r0+8) *AS_STRIDE + k + qd + 4]);
            }
            #pragma unroll
            for (int nt = 0; nt < 8; nt++) {
                const int c = warp_n + nt*8 + gq;
                uint32_t b0 = __float_as_uint(Bcur[(k + qd    )*BS_STRIDE + c]);
                uint32_t b1 = __float_as_uint(Bcur[(k + qd + 4)*BS_STRIDE + c]);
                mma_tf32(acc[0][nt], af[0], b0, b1);
                mma_tf32(acc[1][nt], af[1], b0, b1);
            }
        }
        if (t + 1 < kTiles) {
            __syncthreads();
            if (t + 2 < kTiles) {
                const float* Ag = Ag0 + (t+2)*32;
                const float* Bg = Bg0 + (size_t)(t+2)*32*N;
                #pragma unroll
                for (int i = 0; i < 4; i++)
                    cp16(a_dst0 + stage*A_STG_BYTES + i*32*AS_STRIDE*4, Ag + (size_t)i*32*K);
                #pragma unroll
                for (int i = 0; i < 4; i++)
                    cp16(b_dst0 + stage*B_STG_BYTES + i*8*BS_STRIDE*4, Bg + (size_t)i*8*N);
            }
            asm volatile("cp.async.commit_group;");
            asm volatile("cp.async.wait_group 1;");
            __syncthreads();
        }
    }

    // epilogue
    const bool gelu_tile = (MODE == 1) && (n0 >= 1536);
    #pragma unroll
    for (int mt = 0; mt < 2; mt++) {
        const int r0 = m0 + warp_m + mt*16 + gq;
        #pragma unroll
        for (int nt = 0; nt < 8; nt++) {
            const int c = n0 + warp_n + nt*8 + 2*qd;
            if (MODE == 1) {
                if (gelu_tile) {
                    // gelu(acc) -> g_cat[row*VP + (c - 1024)] tf32-rounded
                    #pragma unroll
                    for (int hh = 0; hh < 2; hh++) {
                        int rr = r0 + hh*8;
                        float v0 = acc[mt][nt][hh*2+0], v1 = acc[mt][nt][hh*2+1];
                        float gl0 = 0.5f*v0*(1.f + erff(v0*0.70710678118654752f));
                        float gl1 = 0.5f*v1*(1.f + erff(v1*0.70710678118654752f));
                        *(float2*)&g_cat[(size_t)rr*VP + (c - 1024)] =
                            make_float2(f2tf32(gl0), f2tf32(gl1));
                    }
                } else {
                    #pragma unroll
                    for (int hh = 0; hh < 2; hh++) {
                        int rr = r0 + hh*8;
                        *(float2*)&C[(size_t)rr*N + c] =
                            make_float2(f2tf32(acc[mt][nt][hh*2+0]), f2tf32(acc[mt][nt][hh*2+1]));
                    }
                }
            } else {
                float bx = bias ? bias[c] : 0.f;
                float by = bias ? bias[c+1] : 0.f;
                *(float2*)&C[(size_t)r0    *N + c] = make_float2(acc[mt][nt][0]+bx, acc[mt][nt][1]+by);
                *(float2*)&C[(size_t)(r0+8)*N + c] = make_float2(acc[mt][nt][2]+bx, acc[mt][nt][3]+by);
            }
        }
    }
}

// ---------------- flash attention, tf32 mma + cp.async double buffer ----------
// g_proj q/k/v already tf32-rounded by tgemm1 epilogue
#define KST 68
#define VST 72
__global__ void __launch_bounds__(128) attn_mma_kernel()
{
    extern __shared__ float smem[];
    float* Kb[2] = { smem, smem + 64*KST };
    float* Vb[2] = { smem + 2*64*KST, smem + 2*64*KST + 64*VST };
    float* Ps    = smem + 2*64*KST + 2*64*VST;     // 64*KST (also Q staging)

    const int qb = gridDim.x - 1 - blockIdx.x;     // longest-running CTAs first
    const int h  = blockIdx.y;
    const int b  = blockIdx.z;
    const int q0 = qb*64;
    const int tid  = threadIdx.x;
    const int warp = tid >> 5;
    const int lane = tid & 31;
    const int gq = lane >> 2;
    const int qd = lane & 3;

    const float scale = 0.125f;
    const float slope = exp2f(-(float)(h+1));

    const uint32_t k_u[2] = { (uint32_t)__cvta_generic_to_shared(Kb[0]),
                              (uint32_t)__cvta_generic_to_shared(Kb[1]) };
    const uint32_t v_u[2] = { (uint32_t)__cvta_generic_to_shared(Vb[0]),
                              (uint32_t)__cvta_generic_to_shared(Vb[1]) };
    const uint32_t p_u    = (uint32_t)__cvta_generic_to_shared(Ps);

    const int chunk_r = tid >> 4;            // 0..7   (8 rows per pass)
    const int chunk_c = (tid & 15) << 2;     // 0..60

    // ---- prologue: Q into Ps, tile 0 K/V into stage 0  (group 0)
    {
        const float* qbase = g_proj + (size_t)(b*SEQ + q0 + chunk_r)*QKVP + h*HD + chunk_c;
        #pragma unroll
        for (int i = 0; i < 8; i++)
            cp16(p_u + (((chunk_r + i*8)*KST + chunk_c) << 2), qbase + (size_t)i*8*QKVP);
        const float* kvb = g_proj + (size_t)(b*SEQ + 0 + chunk_r)*QKVP + h*HD + chunk_c;
        #pragma unroll
        for (int i = 0; i < 8; i++) {
            cp16(k_u[0] + (((chunk_r + i*8)*KST + chunk_c) << 2), kvb + (size_t)i*8*QKVP + 512);
            cp16(v_u[0] + (((chunk_r + i*8)*VST + chunk_c) << 2), kvb + (size_t)i*8*QKVP + 1024);
        }
        asm volatile("cp.async.commit_group;");
    }
    const int ntiles = qb + 1;
    // ---- group 1: tile 1 (or empty)
    if (ntiles > 1) {
        const float* kvb = g_proj + (size_t)(b*SEQ + 64 + chunk_r)*QKVP + h*HD + chunk_c;
        #pragma unroll
        for (int i = 0; i < 8; i++) {
            cp16(k_u[1] + (((chunk_r + i*8)*KST + chunk_c) << 2), kvb + (size_t)i*8*QKVP + 512);
            cp16(v_u[1] + (((chunk_r + i*8)*VST + chunk_c) << 2), kvb + (size_t)i*8*QKVP + 1024);
        }
    }
    asm volatile("cp.async.commit_group;");
    asm volatile("cp.async.wait_group 1;");    // Q + tile0 ready
    __syncthreads();

    // ---- Q fragments to registers
    uint32_t qf[8][4];
    {
        int r0 = warp*16 + gq;
        #pragma unroll
        for (int kt = 0; kt < 8; kt++) {
            int k0 = kt*8;
            qf[kt][0] = __float_as_uint(Ps[ r0     *KST + k0 + qd    ]);
            qf[kt][1] = __float_as_uint(Ps[(r0+8)  *KST + k0 + qd    ]);
            qf[kt][2] = __float_as_uint(Ps[ r0     *KST + k0 + qd + 4]);
            qf[kt][3] = __float_as_uint(Ps[(r0+8)  *KST + k0 + qd + 4]);
        }
    }

    float o[8][4];
    #pragma unroll
    for (int t = 0; t < 8; t++) { o[t][0]=0.f; o[t][1]=0.f; o[t][2]=0.f; o[t][3]=0.f; }
    float m0 = -INFINITY, m1 = -INFINITY, l0 = 0.f, l1 = 0.f;
    const int i0 = q0 + warp*16 + gq;
    const int i1 = i0 + 8;
    const int prow0 = (warp*16 + gq)*KST;
    const int prow1 = (warp*16 + gq + 8)*KST;

    for (int jt = 0; jt < ntiles; jt++) {
        const int j0 = jt*64;
        const int st = jt & 1;
        const float* Ks = Kb[st];
        const float* Vs = Vb[st];

        // ---- S = Q @ K^T
        float s[8][4];
        #pragma unroll
        for (int t = 0; t < 8; t++) { s[t][0]=0.f; s[t][1]=0.f; s[t][2]=0.f; s[t][3]=0.f; }
        #pragma unroll
        for (int kt = 0; kt < 8; kt++) {
            int k0 = kt*8;
            #pragma unroll
            for (int nt = 0; nt < 8; nt++) {
                int n0 = nt*8;
                uint32_t b0 = __float_as_uint(Ks[(n0+gq)*KST + k0 + qd    ]);
                uint32_t b1 = __float_as_uint(Ks[(n0+gq)*KST + k0 + qd + 4]);
                mma_tf32(s[nt], qf[kt], b0, b1);
            }
        }

        // ---- mask/scale/alibi + online softmax
        float rm0 = -INFINITY, rm1 = -INFINITY;
        #pragma unroll
        for (int nt = 0; nt < 8; nt++) {
            int j = j0 + nt*8 + 2*qd;
            s[nt][0] = (j   <= i0) ? fmaf(s[nt][0], scale, slope*(float)j    ) : -1e30f;
            s[nt][1] = (j+1 <= i0) ? fmaf(s[nt][1], scale, slope*(float)(j+1)) : -1e30f;
            s[nt][2] = (j   <= i1) ? fmaf(s[nt][2], scale, slope*(float)j    ) : -1e30f;
            s[nt][3] = (j+1 <= i1) ? fmaf(s[nt][3], scale, slope*(float)(j+1)) : -1e30f;
            rm0 = fmaxf(rm0, fmaxf(s[nt][0], s[nt][1]));
            rm1 = fmaxf(rm1, fmaxf(s[nt][2], s[nt][3]));
        }
        rm0 = fmaxf(rm0, __shfl_xor_sync(0xffffffffu, rm0, 1));
        rm0 = fmaxf(rm0, __shfl_xor_sync(0xffffffffu, rm0, 2));
        rm1 = fmaxf(rm1, __shfl_xor_sync(0xffffffffu, rm1, 1));
        rm1 = fmaxf(rm1, __shfl_xor_sync(0xffffffffu, rm1, 2));
        float nm0 = fmaxf(m0, rm0), nm1 = fmaxf(m1, rm1);
        float c0 = __expf(m0 - nm0), c1 = __expf(m1 - nm1);
        m0 = nm0; m1 = nm1;
        float ps0 = 0.f, ps1 = 0.f;
        #pragma unroll
        for (int nt = 0; nt < 8; nt++) {
            float p0 = __expf(s[nt][0] - nm0);
            float p1 = __expf(s[nt][1] - nm0);
            float p2 = __expf(s[nt][2] - nm1);
            float p3 = __expf(s[nt][3] - nm1);
            ps0 += p0 + p1;  ps1 += p2 + p3;
            int cl = nt*8 + 2*qd;
            *(float2*)&Ps[prow0 + cl] = make_float2(f2tf32(p0), f2tf32(p1));
            *(float2*)&Ps[prow1 + cl] = make_float2(f2tf32(p2), f2tf32(p3));
            o[nt][0] *= c0; o[nt][1] *= c0; o[nt][2] *= c1; o[nt][3] *= c1;
        }
        ps0 += __shfl_xor_sync(0xffffffffu, ps0, 1);
        ps0 += __shfl_xor_sync(0xffffffffu, ps0, 2);
        ps1 += __shfl_xor_sync(0xffffffffu, ps1, 1);
        ps1 += __shfl_xor_sync(0xffffffffu, ps1, 2);
        l0 = l0*c0 + ps0;
        l1 = l1*c1 + ps1;
        __syncwarp();

        // ---- O += P @ V
        #pragma unroll
        for (int kt = 0; kt < 8; kt++) {
            int k0 = kt*8;
            uint32_t pa[4];
            pa[0] = __float_as_uint(Ps[prow0 + k0 + qd    ]);
            pa[1] = __float_as_uint(Ps[prow1 + k0 + qd    ]);
            pa[2] = __float_as_uint(Ps[prow0 + k0 + qd + 4]);
            pa[3] = __float_as_uint(Ps[prow1 + k0 + qd + 4]);
            #pragma unroll
            for (int nt = 0; nt < 8; nt++) {
                int n0 = nt*8;
                uint32_t b0 = __float_as_uint(Vs[(k0+qd  )*VST + n0 + gq]);
                uint32_t b1 = __float_as_uint(Vs[(k0+qd+4)*VST + n0 + gq]);
                mma_tf32(o[nt], pa, b0, b1);
            }
        }
        __syncthreads();                       // done reading stage st

        if (jt + 1 < ntiles) {
            if (jt + 2 < ntiles) {             // prefetch tile jt+2 into freed stage
                const int jn = (jt+2)*64;
                const float* kvb = g_proj + (size_t)(b*SEQ + jn + chunk_r)*QKVP + h*HD + chunk_c;
                #pragma unroll
                for (int i = 0; i < 8; i++) {
                    cp16(k_u[st] + (((chunk_r + i*8)*KST + chunk_c) << 2), kvb + (size_t)i*8*QKVP + 512);
                    cp16(v_u[st] + (((chunk_r + i*8)*VST + chunk_c) << 2), kvb + (size_t)i*8*QKVP + 1024);
                }
            }
            asm volatile("cp.async.commit_group;");
            asm volatile("cp.async.wait_group 1;");  // tile jt+1 ready
            __syncthreads();
        }
    }

    // ---- finalize (tf32-rounded: feeds tgemm2 A)
    float inv0 = 1.f / l0, inv1 = 1.f / l1;
    size_t ob0 = (size_t)(b*SEQ + i0)*VP + h*HD;
    size_t ob1 = (size_t)(b*SEQ + i1)*VP + h*HD;
    #pragma unroll
    for (int nt = 0; nt < 8; nt++) {
        int cl = nt*8 + 2*qd;
        *(float2*)&g_cat[ob0 + cl] = make_float2(f2tf32(o[nt][0]*inv0), f2tf32(o[nt][1]*inv0));
        *(float2*)&g_cat[ob1 + cl] = make_float2(f2tf32(o[nt][2]*inv1), f2tf32(o[nt][3]*inv1));
    }
}

// ---------------- launch ----------------
extern "C" void kernel_launch(void* const* d_in, const int* in_sizes, int n_in,
                              void* d_out, int out_size)
{
    (void)in_sizes; (void)n_in; (void)out_size;
    const float* x     = (const float*)d_in[0];
    const float* gamma = (const float*)d_in[1];
    const float* beta  = (const float*)d_in[2];
    const float* w_in  = (const float*)d_in[3];
    const float* w_out = (const float*)d_in[4];
    const float* b_out = (const float*)d_in[5];
    float* out = (float*)d_out;

    float *p_xt, *p_cat, *p_proj, *p_w1, *p_w2;
    cudaGetSymbolAddress((void**)&p_xt,   g_xt);
    cudaGetSymbolAddress((void**)&p_proj, g_proj);
    cudaGetSymbolAddress((void**)&p_cat,  g_cat);
    cudaGetSymbolAddress((void**)&p_w1,   g_w1);
    cudaGetSymbolAddress((void**)&p_w2,   g_w2);

    cvt_kernel<<<(HIDDEN*QKVP/4 + 255)/256, 256>>>(w_in,  p_w1, HIDDEN*QKVP);
    cvt_kernel<<<(VP*HIDDEN/4   + 255)/256, 256>>>(w_out, p_w2, VP*HIDDEN);

    ln_kernel<<<ROWS, 128>>>(x, gamma, beta);
    feat_kernel<<<(ROWS*HIDDEN + 255)/256, 256>>>();
    scan_kernel<<<BATCH*64, 256>>>();

    int gemm_smem = (2*128*AS_STRIDE + 2*32*BS_STRIDE) * sizeof(float);   // 71680
    cudaFuncSetAttribute(tgemm_kernel<1>, cudaFuncAttributeMaxDynamicSharedMemorySize, gemm_smem);
    cudaFuncSetAttribute(tgemm_kernel<0>, cudaFuncAttributeMaxDynamicSharedMemorySize, gemm_smem);

    dim3 g1(QKVP/128, ROWS/128);     // (28, 32) — gelu fused for cols >= 1536
    tgemm_kernel<1><<<g1, 256, gemm_smem>>>(p_xt, p_w1, p_proj, nullptr, ROWS, QKVP, HIDDEN);

    int attn_smem = (2*64*KST + 2*64*VST + 64*KST) * sizeof(float);       // 89088
    cudaFuncSetAttribute(attn_mma_kernel, cudaFuncAttributeMaxDynamicSharedMemorySize, attn_smem);
    attn_mma_kernel<<<dim3(SEQ/64, HEADS, BATCH), 128, attn_smem>>>();

    dim3 g2(HIDDEN/128, ROWS/128);   // (4, 32)
    tgemm_kernel<0><<<g2, 256, gemm_smem>>>(p_cat, p_w2, out, b_out, ROWS, HIDDEN, VP);
}

// round 6
// speedup vs baseline: 5.9885x; 1.0351x over previous
#include <cuda_runtime.h>
#include <math.h>
#include <stdint.h>

#define BATCH  2
#define SEQ    2048
#define ROWS   (BATCH*SEQ)     // 4096
#define HIDDEN 512
#define QKVP   3584            // HIDDEN*(3+EXP)
#define VP     2560            // HIDDEN*(1+EXP)
#define HEADS  8
#define HD     64
#define KSPLITS 4
#define KSPLIT  (VP/KSPLITS)   // 640

// ---------------- scratch (no cudaMalloc allowed) ----------------
__device__ float g_xn[(size_t)ROWS*HIDDEN];          //  8 MB
__device__ float g_xt[(size_t)ROWS*HIDDEN];          //  8 MB   (tf32-rounded)
__device__ float g_proj[(size_t)ROWS*QKVP];          // q,k,v tf32-rounded (p fused away)
__device__ float g_cat[(size_t)ROWS*VP];             // 41.9 MB (tf32-rounded)
__device__ float g_w1[(size_t)HIDDEN*QKVP];          //  7.3 MB (tf32 w_in)
__device__ float g_w2[(size_t)VP*HIDDEN];            //  5.2 MB (tf32 w_out)
__device__ float g_part[(size_t)KSPLITS*ROWS*HIDDEN];// 33.5 MB split-K partials

// ---------------- tf32 helpers ----------------
__device__ __forceinline__ float f2tf32(float x) {
    uint32_t r;
    asm("cvt.rna.tf32.f32 %0, %1;" : "=r"(r) : "f"(x));
    return __uint_as_float(r);
}
__device__ __forceinline__ void mma_tf32(float* d, const uint32_t* a, uint32_t b0, uint32_t b1) {
    asm volatile("mma.sync.aligned.m16n8k8.row.col.f32.tf32.tf32.f32 "
        "{%0,%1,%2,%3}, {%4,%5,%6,%7}, {%8,%9}, {%0,%1,%2,%3};"
        : "+f"(d[0]), "+f"(d[1]), "+f"(d[2]), "+f"(d[3])
        : "r"(a[0]), "r"(a[1]), "r"(a[2]), "r"(a[3]), "r"(b0), "r"(b1));
}
__device__ __forceinline__ void cp16(uint32_t dst, const void* src) {
    asm volatile("cp.async.cg.shared.global [%0], [%1], 16;" :: "r"(dst), "l"(src));
}

// ---------------- weight pre-round to tf32 ----------------
__global__ void cvt_kernel(const float* __restrict__ src, float* __restrict__ dst, int n)
{
    int i = blockIdx.x*256 + threadIdx.x;
    if (i*4 >= n) return;
    float4 v = *(const float4*)&src[i*4];
    float4 o = make_float4(f2tf32(v.x), f2tf32(v.y), f2tf32(v.z), f2tf32(v.w));
    *(float4*)&dst[i*4] = o;
}

// ---------------- LayerNorm (+ fused ident feature copy) ----------------
__global__ void __launch_bounds__(128) ln_kernel(const float* __restrict__ x,
                                                 const float* __restrict__ gamma,
                                                 const float* __restrict__ beta)
{
    int row = blockIdx.x;
    int tid = threadIdx.x;
    const float* xr = x + (size_t)row*HIDDEN;
    float v[4];
    float s = 0.f;
    #pragma unroll
    for (int i = 0; i < 4; i++) { v[i] = xr[tid + i*128]; s += v[i]; }
    __shared__ float red[4];
    #pragma unroll
    for (int o = 16; o > 0; o >>= 1) s += __shfl_xor_sync(0xffffffffu, s, o);
    if ((tid & 31) == 0) red[tid >> 5] = s;
    __syncthreads();
    float mu = (red[0]+red[1]+red[2]+red[3]) * (1.f/HIDDEN);
    float vs = 0.f;
    #pragma unroll
    for (int i = 0; i < 4; i++) { float d = v[i]-mu; vs += d*d; }
    #pragma unroll
    for (int o = 16; o > 0; o >>= 1) vs += __shfl_xor_sync(0xffffffffu, vs, o);
    __syncthreads();
    if ((tid & 31) == 0) red[tid >> 5] = vs;
    __syncthreads();
    float var  = (red[0]+red[1]+red[2]+red[3]) * (1.f/HIDDEN);
    float rstd = rsqrtf(var + 1e-5f);
    #pragma unroll
    for (int i = 0; i < 4; i++) {
        int c = tid + i*128;
        float xn = (v[i]-mu)*rstd*gamma[c] + beta[c];
        g_xn[(size_t)row*HIDDEN + c] = xn;
        if (c < 320) g_xt[(size_t)row*HIDDEN + c] = f2tf32(xn);   // ident slice fused
    }
}

// ---------------- feature transform: shift channels only ----------------
__global__ void feat_kernel()
{
    int idx = blockIdx.x*256 + threadIdx.x;            // ROWS*128 threads
    if (idx >= ROWS*128) return;
    int c   = 384 + (idx & 127);
    int row = idx >> 7;
    int i   = row & (SEQ-1);
    size_t base = (size_t)row*HIDDEN + c;
    float val;
    if (c < 448)  val = (i >= 1) ? g_xn[base -   HIDDEN] : 0.f;
    else          val = (i >= 2) ? g_xn[base - 2*HIDDEN] : 0.f;
    g_xt[base] = f2tf32(val);
}

// ---------------- cumlogsumexp scan (tf32-rounded out) ----------------
__global__ void __launch_bounds__(256) scan_kernel()
{
    int bc  = blockIdx.x;
    int b   = bc >> 6;
    int ch  = 320 + (bc & 63);
    int tid = threadIdx.x;
    int row0 = b*SEQ + tid*8;
    float y[8];
    #pragma unroll
    for (int i = 0; i < 8; i++) y[i] = 5.f * g_xn[(size_t)(row0+i)*HIDDEN + ch];
    float m = -INFINITY, s = 0.f;
    #pragma unroll
    for (int i = 0; i < 8; i++) {
        float M = fmaxf(m, y[i]);
        s = s*expf(m - M) + expf(y[i] - M);
        m = M;
    }
    __shared__ float sm[256], ss[256];
    sm[tid] = m; ss[tid] = s;
    __syncthreads();
    for (int off = 1; off < 256; off <<= 1) {
        float pm = 0.f, ps = 0.f;
        bool act = (tid >= off);
        if (act) { pm = sm[tid-off]; ps = ss[tid-off]; }
        __syncthreads();
        if (act) {
            float M = fmaxf(pm, m);
            s = ps*expf(pm - M) + s*expf(m - M);
            m = M;
            sm[tid] = m; ss[tid] = s;
        }
        __syncthreads();
    }
    float pm = -INFINITY, ps = 0.f;
    if (tid > 0) { pm = sm[tid-1]; ps = ss[tid-1]; }
    #pragma unroll
    for (int i = 0; i < 8; i++) {
        float M = fmaxf(pm, y[i]);
        ps = ps*expf(pm - M) + expf(y[i] - M);
        pm = M;
        g_xt[(size_t)(row0+i)*HIDDEN + ch] = f2tf32((pm + logf(ps)) * 0.2f);
    }
}

// ---------------- tf32 tensor GEMM w/ cp.async, 2-stage ----------------------
// MODE 1: proj mode — cols < 1536: f2tf32 -> C (g_proj);
//                     cols >= 1536: gelu(acc) -> g_cat[row*VP + c - 1024] (tf32)
// MODE 2: split-K partial — blockIdx.z selects K slice; plain fp32 -> C + z*M*N
#define AS_STRIDE 36    // = 4 (mod 32)
#define BS_STRIDE 136   // = 8 (mod 32)
#define A_STG_BYTES (128*AS_STRIDE*4)
#define B_STG_BYTES (32*BS_STRIDE*4)
template<int MODE>
__global__ void __launch_bounds__(256, 2) tgemm_kernel(
    const float* __restrict__ A, const float* __restrict__ B,
    float* __restrict__ C,
    int M, int N, int K, int lda)
{
    extern __shared__ float smbuf[];
    float* As = smbuf;
    float* Bs = smbuf + 2*128*AS_STRIDE;

    if (MODE == 2) {
        const int z = blockIdx.z;
        A += (size_t)z*K;             // K columns ahead (lda = full row stride)
        B += (size_t)z*K*N;
        C += (size_t)z*M*N;
    }

    const int tid  = threadIdx.x;
    const int warp = tid >> 5;
    const int lane = tid & 31;
    const int gq = lane >> 2;
    const int qd = lane & 3;
    const int warp_m = (warp & 3) * 32;
    const int warp_n = (warp >> 2) * 64;
    const int m0 = blockIdx.y * 128;
    const int n0 = blockIdx.x * 128;

    const int a_r = tid >> 3;
    const int a_c = (tid & 7) << 2;
    const int b_r = tid >> 5;
    const int b_c = (tid & 31) << 2;

    const uint32_t as_u = (uint32_t)__cvta_generic_to_shared(As);
    const uint32_t bs_u = (uint32_t)__cvta_generic_to_shared(Bs);
    const uint32_t a_dst0 = as_u + ((uint32_t)(a_r*AS_STRIDE + a_c) << 2);
    const uint32_t b_dst0 = bs_u + ((uint32_t)(b_r*BS_STRIDE + b_c) << 2);

    const float* Ag0 = A + (size_t)(m0 + a_r)*lda + a_c;
    const float* Bg0 = B + (size_t)b_r*N + n0 + b_c;

    const int kTiles = K >> 5;

    #pragma unroll
    for (int s = 0; s < 2; s++) {
        if (s < kTiles) {
            const float* Ag = Ag0 + s*32;
            const float* Bg = Bg0 + (size_t)s*32*N;
            #pragma unroll
            for (int i = 0; i < 4; i++)
                cp16(a_dst0 + s*A_STG_BYTES + i*32*AS_STRIDE*4, Ag + (size_t)i*32*lda);
            #pragma unroll
            for (int i = 0; i < 4; i++)
                cp16(b_dst0 + s*B_STG_BYTES + i*8*BS_STRIDE*4, Bg + (size_t)i*8*N);
        }
        asm volatile("cp.async.commit_group;");
    }
    asm volatile("cp.async.wait_group 1;");
    __syncthreads();

    float acc[2][8][4];
    #pragma unroll
    for (int mt = 0; mt < 2; mt++)
        #pragma unroll
        for (int nt = 0; nt < 8; nt++)
            #pragma unroll
            for (int i = 0; i < 4; i++) acc[mt][nt][i] = 0.f;

    for (int t = 0; t < kTiles; t++) {
        const int stage = t & 1;
        const float* Acur = As + stage*128*AS_STRIDE;
        const float* Bcur = Bs + stage*32*BS_STRIDE;
        #pragma unroll
        for (int kk = 0; kk < 4; kk++) {
            const int k = kk*8;
            uint32_t af[2][4];
            #pragma unroll
            for (int mt = 0; mt < 2; mt++) {
                const int r0 = warp_m + mt*16 + gq;
                af[mt][0] = __float_as_uint(Acur[ r0    *AS_STRIDE + k + qd    ]);
                af[mt][1] = __float_as_uint(Acur[(r0+8) *AS_STRIDE + k + qd    ]);
                af[mt][2] = __float_as_uint(Acur[ r0    *AS_STRIDE + k + qd + 4]);
                af[mt][3] = __float_as_uint(Acur[(r0+8) *AS_STRIDE + k + qd + 4]);
            }
            #pragma unroll
            for (int nt = 0; nt < 8; nt++) {
                const int c = warp_n + nt*8 + gq;
                uint32_t b0 = __float_as_uint(Bcur[(k + qd    )*BS_STRIDE + c]);
                uint32_t b1 = __float_as_uint(Bcur[(k + qd + 4)*BS_STRIDE + c]);
                mma_tf32(acc[0][nt], af[0], b0, b1);
                mma_tf32(acc[1][nt], af[1], b0, b1);
            }
        }
        if (t + 1 < kTiles) {
            __syncthreads();
            if (t + 2 < kTiles) {
                const float* Ag = Ag0 + (t+2)*32;
                const float* Bg = Bg0 + (size_t)(t+2)*32*N;
                #pragma unroll
                for (int i = 0; i < 4; i++)
                    cp16(a_dst0 + stage*A_STG_BYTES + i*32*AS_STRIDE*4, Ag + (size_t)i*32*lda);
                #pragma unroll
                for (int i = 0; i < 4; i++)
                    cp16(b_dst0 + stage*B_STG_BYTES + i*8*BS_STRIDE*4, Bg + (size_t)i*8*N);
            }
            asm volatile("cp.async.commit_group;");
            asm volatile("cp.async.wait_group 1;");
            __syncthreads();
        }
    }

    // epilogue
    const bool gelu_tile = (MODE == 1) && (n0 >= 1536);
    #pragma unroll
    for (int mt = 0; mt < 2; mt++) {
        const int r0 = m0 + warp_m + mt*16 + gq;
        #pragma unroll
        for (int nt = 0; nt < 8; nt++) {
            const int c = n0 + warp_n + nt*8 + 2*qd;
            if (MODE == 1) {
                if (gelu_tile) {
                    #pragma unroll
                    for (int hh = 0; hh < 2; hh++) {
                        int rr = r0 + hh*8;
                        float v0 = acc[mt][nt][hh*2+0], v1 = acc[mt][nt][hh*2+1];
                        float gl0 = 0.5f*v0*(1.f + erff(v0*0.70710678118654752f));
                        float gl1 = 0.5f*v1*(1.f + erff(v1*0.70710678118654752f));
                        *(float2*)&g_cat[(size_t)rr*VP + (c - 1024)] =
                            make_float2(f2tf32(gl0), f2tf32(gl1));
                    }
                } else {
                    #pragma unroll
                    for (int hh = 0; hh < 2; hh++) {
                        int rr = r0 + hh*8;
                        *(float2*)&C[(size_t)rr*N + c] =
                            make_float2(f2tf32(acc[mt][nt][hh*2+0]), f2tf32(acc[mt][nt][hh*2+1]));
                    }
                }
            } else {   // MODE 2: raw partial
                *(float2*)&C[(size_t)r0    *N + c] = make_float2(acc[mt][nt][0], acc[mt][nt][1]);
                *(float2*)&C[(size_t)(r0+8)*N + c] = make_float2(acc[mt][nt][2], acc[mt][nt][3]);
            }
        }
    }
}

// ---------------- split-K reduce + bias ----------------
__global__ void reduce_kernel(float* __restrict__ out, const float* __restrict__ bias)
{
    int i = blockIdx.x*256 + threadIdx.x;          // float4 index
    if (i >= ROWS*HIDDEN/4) return;
    size_t off = (size_t)i*4;
    const size_t stride = (size_t)ROWS*HIDDEN;
    float4 a = *(const float4*)&g_part[off];
    float4 b = *(const float4*)&g_part[off + stride];
    float4 c = *(const float4*)&g_part[off + 2*stride];
    float4 d = *(const float4*)&g_part[off + 3*stride];
    int col = (int)(off & (HIDDEN-1));
    float4 bb = *(const float4*)&bias[col];
    float4 r;
    r.x = a.x + b.x + c.x + d.x + bb.x;
    r.y = a.y + b.y + c.y + d.y + bb.y;
    r.z = a.z + b.z + c.z + d.z + bb.z;
    r.w = a.w + b.w + c.w + d.w + bb.w;
    *(float4*)&out[off] = r;
}

// ---------------- flash attention: tf32 mma, cp.async 2-stage, P overlaid -----
// smem/stage: K 64xKST then V 64xVST; P reuses the K region (legalized by sync)
#define KST 68
#define VST 72
#define STG_FLOATS (64*KST + 64*VST)
__global__ void __launch_bounds__(128, 3) attn_mma_kernel()
{
    extern __shared__ float smem[];
    float* stg[2] = { smem, smem + STG_FLOATS };

    const int qb = gridDim.x - 1 - blockIdx.x;     // longest CTAs first
    const int h  = blockIdx.y;
    const int b  = blockIdx.z;
    const int q0 = qb*64;
    const int tid  = threadIdx.x;
    const int warp = tid >> 5;
    const int lane = tid & 31;
    const int gq = lane >> 2;
    const int qd = lane & 3;

    const float scale = 0.125f;
    const float slope = exp2f(-(float)(h+1));

    const uint32_t s_u[2] = { (uint32_t)__cvta_generic_to_shared(stg[0]),
                              (uint32_t)__cvta_generic_to_shared(stg[1]) };

    const int chunk_r = tid >> 4;            // 0..7
    const int chunk_c = (tid & 15) << 2;     // 0..60

    const int ntiles = qb + 1;

    // ---- group A: Q -> stage1 K region, tile0 K/V -> stage0
    {
        const float* qbase = g_proj + (size_t)(b*SEQ + q0 + chunk_r)*QKVP + h*HD + chunk_c;
        #pragma unroll
        for (int i = 0; i < 8; i++)
            cp16(s_u[1] + (((chunk_r + i*8)*KST + chunk_c) << 2), qbase + (size_t)i*8*QKVP);
        const float* kvb = g_proj + (size_t)(b*SEQ + chunk_r)*QKVP + h*HD + chunk_c;
        #pragma unroll
        for (int i = 0; i < 8; i++) {
            cp16(s_u[0] + (((chunk_r + i*8)*KST + chunk_c) << 2),            kvb + (size_t)i*8*QKVP + 512);
            cp16(s_u[0] + ((64*KST + (chunk_r + i*8)*VST + chunk_c) << 2),   kvb + (size_t)i*8*QKVP + 1024);
        }
        asm volatile("cp.async.commit_group;");
    }
    asm volatile("cp.async.wait_group 0;");
    __syncthreads();

    // ---- Q fragments from stage1 K region
    uint32_t qf[8][4];
    {
        const float* Qs = stg[1];
        int r0 = warp*16 + gq;
        #pragma unroll
        for (int kt = 0; kt < 8; kt++) {
            int k0 = kt*8;
            qf[kt][0] = __float_as_uint(Qs[ r0     *KST + k0 + qd    ]);
            qf[kt][1] = __float_as_uint(Qs[(r0+8)  *KST + k0 + qd    ]);
            qf[kt][2] = __float_as_uint(Qs[ r0     *KST + k0 + qd + 4]);
            qf[kt][3] = __float_as_uint(Qs[(r0+8)  *KST + k0 + qd + 4]);
        }
    }
    __syncthreads();                               // all warps done with Q staging

    // ---- group B: tile1 -> stage1 (overwrites Q staging)
    if (ntiles > 1) {
        const float* kvb = g_proj + (size_t)(b*SEQ + 64 + chunk_r)*QKVP + h*HD + chunk_c;
        #pragma unroll
        for (int i = 0; i < 8; i++) {
            cp16(s_u[1] + (((chunk_r + i*8)*KST + chunk_c) << 2),          kvb + (size_t)i*8*QKVP + 512);
            cp16(s_u[1] + ((64*KST + (chunk_r + i*8)*VST + chunk_c) << 2), kvb + (size_t)i*8*QKVP + 1024);
        }
        asm volatile("cp.async.commit_group;");
    }

    float o[8][4];
    #pragma unroll
    for (int t = 0; t < 8; t++) { o[t][0]=0.f; o[t][1]=0.f; o[t][2]=0.f; o[t][3]=0.f; }
    float m0 = -INFINITY, m1 = -INFINITY, l0 = 0.f, l1 = 0.f;
    const int i0 = q0 + warp*16 + gq;
    const int i1 = i0 + 8;
    const int prow0 = (warp*16 + gq)*KST;
    const int prow1 = (warp*16 + gq + 8)*KST;

    for (int jt = 0; jt < ntiles; jt++) {
        const int j0 = jt*64;
        const int st = jt & 1;
        float* Ks = stg[st];                 // also the P buffer after QK
        const float* Vs = stg[st] + 64*KST;

        // ---- S = Q @ K^T
        float s[8][4];
        #pragma unroll
        for (int t = 0; t < 8; t++) { s[t][0]=0.f; s[t][1]=0.f; s[t][2]=0.f; s[t][3]=0.f; }
        #pragma unroll
        for (int kt = 0; kt < 8; kt++) {
            int k0 = kt*8;
            #pragma unroll
            for (int nt = 0; nt < 8; nt++) {
                int n0 = nt*8;
                uint32_t b0 = __float_as_uint(Ks[(n0+gq)*KST + k0 + qd    ]);
                uint32_t b1 = __float_as_uint(Ks[(n0+gq)*KST + k0 + qd + 4]);
                mma_tf32(s[nt], qf[kt], b0, b1);
            }
        }

        // ---- mask/scale/alibi + online softmax (registers only)
        float rm0 = -INFINITY, rm1 = -INFINITY;
        #pragma unroll
        for (int nt = 0; nt < 8; nt++) {
            int j = j0 + nt*8 + 2*qd;
            s[nt][0] = (j   <= i0) ? fmaf(s[nt][0], scale, slope*(float)j    ) : -1e30f;
            s[nt][1] = (j+1 <= i0) ? fmaf(s[nt][1], scale, slope*(float)(j+1)) : -1e30f;
            s[nt][2] = (j   <= i1) ? fmaf(s[nt][2], scale, slope*(float)j    ) : -1e30f;
            s[nt][3] = (j+1 <= i1) ? fmaf(s[nt][3], scale, slope*(float)(j+1)) : -1e30f;
            rm0 = fmaxf(rm0, fmaxf(s[nt][0], s[nt][1]));
            rm1 = fmaxf(rm1, fmaxf(s[nt][2], s[nt][3]));
        }
        rm0 = fmaxf(rm0, __shfl_xor_sync(0xffffffffu, rm0, 1));
        rm0 = fmaxf(rm0, __shfl_xor_sync(0xffffffffu, rm0, 2));
        rm1 = fmaxf(rm1, __shfl_xor_sync(0xffffffffu, rm1, 1));
        rm1 = fmaxf(rm1, __shfl_xor_sync(0xffffffffu, rm1, 2));
        float nm0 = fmaxf(m0, rm0), nm1 = fmaxf(m1, rm1);
        float c0 = __expf(m0 - nm0), c1 = __expf(m1 - nm1);
        m0 = nm0; m1 = nm1;
        float pv[8][4];
        float ps0 = 0.f, ps1 = 0.f;
        #pragma unroll
        for (int nt = 0; nt < 8; nt++) {
            pv[nt][0] = __expf(s[nt][0] - nm0);
            pv[nt][1] = __expf(s[nt][1] - nm0);
            pv[nt][2] = __expf(s[nt][2] - nm1);
            pv[nt][3] = __expf(s[nt][3] - nm1);
            ps0 += pv[nt][0] + pv[nt][1];
            ps1 += pv[nt][2] + pv[nt][3];
            o[nt][0] *= c0; o[nt][1] *= c0; o[nt][2] *= c1; o[nt][3] *= c1;
        }
        ps0 += __shfl_xor_sync(0xffffffffu, ps0, 1);
        ps0 += __shfl_xor_sync(0xffffffffu, ps0, 2);
        ps1 += __shfl_xor_sync(0xffffffffu, ps1, 1);
        ps1 += __shfl_xor_sync(0xffffffffu, ps1, 2);
        l0 = l0*c0 + ps0;
        l1 = l1*c1 + ps1;

        __syncthreads();                     // all warps done reading K -> reuse as P
        #pragma unroll
        for (int nt = 0; nt < 8; nt++) {
            int cl = nt*8 + 2*qd;
            *(float2*)&Ks[prow0 + cl] = make_float2(f2tf32(pv[nt][0]), f2tf32(pv[nt][1]));
            *(float2*)&Ks[prow1 + cl] = make_float2(f2tf32(pv[nt][2]), f2tf32(pv[nt][3]));
        }
        __syncwarp();                        // own rows written by own warp only

        // ---- O += P @ V
        #pragma unroll
        for (int kt = 0; kt < 8; kt++) {
            int k0 = kt*8;
            uint32_t pa[4];
            pa[0] = __float_as_uint(Ks[prow0 + k0 + qd    ]);
            pa[1] = __float_as_uint(Ks[prow1 + k0 + qd    ]);
            pa[2] = __float_as_uint(Ks[prow0 + k0 + qd + 4]);
            pa[3] = __float_as_uint(Ks[prow1 + k0 + qd + 4]);
            #pragma unroll
            for (int nt = 0; nt < 8; nt++) {
                int n0 = nt*8;
                uint32_t b0 = __float_as_uint(Vs[(k0+qd  )*VST + n0 + gq]);
                uint32_t b1 = __float_as_uint(Vs[(k0+qd+4)*VST + n0 + gq]);
                mma_tf32(o[nt], pa, b0, b1);
            }
        }
        __syncthreads();                     // all warps done with stage st

        if (jt + 1 < ntiles) {
            if (jt + 2 < ntiles) {           // prefetch tile jt+2 into freed stage
                const int jn = (jt+2)*64;
                const float* kvb = g_proj + (size_t)(b*SEQ + jn + chunk_r)*QKVP + h*HD + chunk_c;
                #pragma unroll
                for (int i = 0; i < 8; i++) {
                    cp16(s_u[st] + (((chunk_r + i*8)*KST + chunk_c) << 2),          kvb + (size_t)i*8*QKVP + 512);
                    cp16(s_u[st] + ((64*KST + (chunk_r + i*8)*VST + chunk_c) << 2), kvb + (size_t)i*8*QKVP + 1024);
                }
            }
            asm volatile("cp.async.commit_group;");
            asm volatile("cp.async.wait_group 1;");   // tile jt+1 landed
            __syncthreads();
        }
    }

    // ---- finalize (tf32-rounded: feeds tgemm2 A)
    float inv0 = 1.f / l0, inv1 = 1.f / l1;
    size_t ob0 = (size_t)(b*SEQ + i0)*VP + h*HD;
    size_t ob1 = (size_t)(b*SEQ + i1)*VP + h*HD;
    #pragma unroll
    for (int nt = 0; nt < 8; nt++) {
        int cl = nt*8 + 2*qd;
        *(float2*)&g_cat[ob0 + cl] = make_float2(f2tf32(o[nt][0]*inv0), f2tf32(o[nt][1]*inv0));
        *(float2*)&g_cat[ob1 + cl] = make_float2(f2tf32(o[nt][2]*inv1), f2tf32(o[nt][3]*inv1));
    }
}

// ---------------- launch ----------------
extern "C" void kernel_launch(void* const* d_in, const int* in_sizes, int n_in,
                              void* d_out, int out_size)
{
    (void)in_sizes; (void)n_in; (void)out_size;
    const float* x     = (const float*)d_in[0];
    const float* gamma = (const float*)d_in[1];
    const float* beta  = (const float*)d_in[2];
    const float* w_in  = (const float*)d_in[3];
    const float* w_out = (const float*)d_in[4];
    const float* b_out = (const float*)d_in[5];
    float* out = (float*)d_out;

    float *p_xt, *p_cat, *p_proj, *p_w1, *p_w2, *p_part;
    cudaGetSymbolAddress((void**)&p_xt,   g_xt);
    cudaGetSymbolAddress((void**)&p_proj, g_proj);
    cudaGetSymbolAddress((void**)&p_cat,  g_cat);
    cudaGetSymbolAddress((void**)&p_w1,   g_w1);
    cudaGetSymbolAddress((void**)&p_w2,   g_w2);
    cudaGetSymbolAddress((void**)&p_part, g_part);

    cvt_kernel<<<(HIDDEN*QKVP/4 + 255)/256, 256>>>(w_in,  p_w1, HIDDEN*QKVP);
    cvt_kernel<<<(VP*HIDDEN/4   + 255)/256, 256>>>(w_out, p_w2, VP*HIDDEN);

    ln_kernel<<<ROWS, 128>>>(x, gamma, beta);
    feat_kernel<<<(ROWS*128 + 255)/256, 256>>>();
    scan_kernel<<<BATCH*64, 256>>>();

    int gemm_smem = (2*128*AS_STRIDE + 2*32*BS_STRIDE) * sizeof(float);   // 71680
    cudaFuncSetAttribute(tgemm_kernel<1>, cudaFuncAttributeMaxDynamicSharedMemorySize, gemm_smem);
    cudaFuncSetAttribute(tgemm_kernel<2>, cudaFuncAttributeMaxDynamicSharedMemorySize, gemm_smem);

    dim3 g1(QKVP/128, ROWS/128);     // (28, 32) — gelu fused for cols >= 1536
    tgemm_kernel<1><<<g1, 256, gemm_smem>>>(p_xt, p_w1, p_proj, ROWS, QKVP, HIDDEN, HIDDEN);

    int attn_smem = 2*STG_FLOATS*sizeof(float);                           // 71680
    cudaFuncSetAttribute(attn_mma_kernel, cudaFuncAttributeMaxDynamicSharedMemorySize, attn_smem);
    attn_mma_kernel<<<dim3(SEQ/64, HEADS, BATCH), 128, attn_smem>>>();

    dim3 g2(HIDDEN/128, ROWS/128, KSPLITS);   // (4, 32, 4) split-K
    tgemm_kernel<2><<<g2, 256, gemm_smem>>>(p_cat, p_w2, p_part, ROWS, HIDDEN, KSPLIT, VP);
    reduce_kernel<<<(ROWS*HIDDEN/4 + 255)/256, 256>>>(out, b_out);
}

// round 7
// speedup vs baseline: 6.3394x; 1.0586x over previous
#include <cuda_runtime.h>
#include <math.h>
#include <stdint.h>

#define BATCH  2
#define SEQ    2048
#define ROWS   (BATCH*SEQ)     // 4096
#define HIDDEN 512
#define QKVP   3584            // HIDDEN*(3+EXP)
#define VP     2560            // HIDDEN*(1+EXP)
#define HEADS  8
#define HD     64
#define KSPLITS 4
#define KSPLIT  (VP/KSPLITS)   // 640
#define CHUNK_TILES 8          // attention split-K: 8 tiles of 64 keys

// ---------------- scratch (no cudaMalloc allowed) ----------------
__device__ float g_xn[(size_t)ROWS*HIDDEN];          //  8 MB
__device__ float g_xt[(size_t)ROWS*HIDDEN];          //  8 MB   (tf32-rounded)
__device__ float g_proj[(size_t)ROWS*QKVP];          // q,k,v tf32-rounded
__device__ float g_cat[(size_t)ROWS*VP];             // 41.9 MB (tf32-rounded)
__device__ float g_w1[(size_t)HIDDEN*QKVP];          //  7.3 MB (tf32 w_in)
__device__ float g_w2[(size_t)VP*HIDDEN];            //  5.2 MB (tf32 w_out)
__device__ float g_part[(size_t)KSPLITS*ROWS*HIDDEN];// 33.5 MB: attn O-partials, then tgemm2 partials
__device__ float g_ml[(size_t)BATCH*HEADS*32*4*128]; //  1 MB: attn m/l partials

// ---------------- tf32 helpers ----------------
__device__ __forceinline__ float f2tf32(float x) {
    uint32_t r;
    asm("cvt.rna.tf32.f32 %0, %1;" : "=r"(r) : "f"(x));
    return __uint_as_float(r);
}
__device__ __forceinline__ void mma_tf32(float* d, const uint32_t* a, uint32_t b0, uint32_t b1) {
    asm volatile("mma.sync.aligned.m16n8k8.row.col.f32.tf32.tf32.f32 "
        "{%0,%1,%2,%3}, {%4,%5,%6,%7}, {%8,%9}, {%0,%1,%2,%3};"
        : "+f"(d[0]), "+f"(d[1]), "+f"(d[2]), "+f"(d[3])
        : "r"(a[0]), "r"(a[1]), "r"(a[2]), "r"(a[3]), "r"(b0), "r"(b1));
}
__device__ __forceinline__ void cp16(uint32_t dst, const void* src) {
    asm volatile("cp.async.cg.shared.global [%0], [%1], 16;" :: "r"(dst), "l"(src));
}

// ---------------- weight pre-round to tf32 ----------------
__global__ void cvt_kernel(const float* __restrict__ src, float* __restrict__ dst, int n)
{
    int i = blockIdx.x*256 + threadIdx.x;
    if (i*4 >= n) return;
    float4 v = *(const float4*)&src[i*4];
    float4 o = make_float4(f2tf32(v.x), f2tf32(v.y), f2tf32(v.z), f2tf32(v.w));
    *(float4*)&dst[i*4] = o;
}

// ---------------- LayerNorm (+ fused ident feature copy) ----------------
__global__ void __launch_bounds__(128) ln_kernel(const float* __restrict__ x,
                                                 const float* __restrict__ gamma,
                                                 const float* __restrict__ beta)
{
    int row = blockIdx.x;
    int tid = threadIdx.x;
    const float* xr = x + (size_t)row*HIDDEN;
    float v[4];
    float s = 0.f;
    #pragma unroll
    for (int i = 0; i < 4; i++) { v[i] = xr[tid + i*128]; s += v[i]; }
    __shared__ float red[4];
    #pragma unroll
    for (int o = 16; o > 0; o >>= 1) s += __shfl_xor_sync(0xffffffffu, s, o);
    if ((tid & 31) == 0) red[tid >> 5] = s;
    __syncthreads();
    float mu = (red[0]+red[1]+red[2]+red[3]) * (1.f/HIDDEN);
    float vs = 0.f;
    #pragma unroll
    for (int i = 0; i < 4; i++) { float d = v[i]-mu; vs += d*d; }
    #pragma unroll
    for (int o = 16; o > 0; o >>= 1) vs += __shfl_xor_sync(0xffffffffu, vs, o);
    __syncthreads();
    if ((tid & 31) == 0) red[tid >> 5] = vs;
    __syncthreads();
    float var  = (red[0]+red[1]+red[2]+red[3]) * (1.f/HIDDEN);
    float rstd = rsqrtf(var + 1e-5f);
    #pragma unroll
    for (int i = 0; i < 4; i++) {
        int c = tid + i*128;
        float xn = (v[i]-mu)*rstd*gamma[c] + beta[c];
        g_xn[(size_t)row*HIDDEN + c] = xn;
        if (c < 320) g_xt[(size_t)row*HIDDEN + c] = f2tf32(xn);
    }
}

// ---------------- feature transform: shift channels only ----------------
__global__ void feat_kernel()
{
    int idx = blockIdx.x*256 + threadIdx.x;
    if (idx >= ROWS*128) return;
    int c   = 384 + (idx & 127);
    int row = idx >> 7;
    int i   = row & (SEQ-1);
    size_t base = (size_t)row*HIDDEN + c;
    float val;
    if (c < 448)  val = (i >= 1) ? g_xn[base -   HIDDEN] : 0.f;
    else          val = (i >= 2) ? g_xn[base - 2*HIDDEN] : 0.f;
    g_xt[base] = f2tf32(val);
}

// ---------------- cumlogsumexp scan (tf32-rounded out) ----------------
__global__ void __launch_bounds__(256) scan_kernel()
{
    int bc  = blockIdx.x;
    int b   = bc >> 6;
    int ch  = 320 + (bc & 63);
    int tid = threadIdx.x;
    int row0 = b*SEQ + tid*8;
    float y[8];
    #pragma unroll
    for (int i = 0; i < 8; i++) y[i] = 5.f * g_xn[(size_t)(row0+i)*HIDDEN + ch];
    float m = -INFINITY, s = 0.f;
    #pragma unroll
    for (int i = 0; i < 8; i++) {
        float M = fmaxf(m, y[i]);
        s = s*expf(m - M) + expf(y[i] - M);
        m = M;
    }
    __shared__ float sm[256], ss[256];
    sm[tid] = m; ss[tid] = s;
    __syncthreads();
    for (int off = 1; off < 256; off <<= 1) {
        float pm = 0.f, ps = 0.f;
        bool act = (tid >= off);
        if (act) { pm = sm[tid-off]; ps = ss[tid-off]; }
        __syncthreads();
        if (act) {
            float M = fmaxf(pm, m);
            s = ps*expf(pm - M) + s*expf(m - M);
            m = M;
            sm[tid] = m; ss[tid] = s;
        }
        __syncthreads();
    }
    float pm = -INFINITY, ps = 0.f;
    if (tid > 0) { pm = sm[tid-1]; ps = ss[tid-1]; }
    #pragma unroll
    for (int i = 0; i < 8; i++) {
        float M = fmaxf(pm, y[i]);
        ps = ps*expf(pm - M) + expf(y[i] - M);
        pm = M;
        g_xt[(size_t)(row0+i)*HIDDEN + ch] = f2tf32((pm + logf(ps)) * 0.2f);
    }
}

// ---------------- tf32 tensor GEMM w/ cp.async, 2-stage ----------------------
#define AS_STRIDE 36
#define BS_STRIDE 136
#define A_STG_BYTES (128*AS_STRIDE*4)
#define B_STG_BYTES (32*BS_STRIDE*4)
template<int MODE>
__global__ void __launch_bounds__(256, 2) tgemm_kernel(
    const float* __restrict__ A, const float* __restrict__ B,
    float* __restrict__ C,
    int M, int N, int K, int lda)
{
    extern __shared__ float smbuf[];
    float* As = smbuf;
    float* Bs = smbuf + 2*128*AS_STRIDE;

    if (MODE == 2) {
        const int z = blockIdx.z;
        A += (size_t)z*K;
        B += (size_t)z*K*N;
        C += (size_t)z*M*N;
    }

    const int tid  = threadIdx.x;
    const int warp = tid >> 5;
    const int lane = tid & 31;
    const int gq = lane >> 2;
    const int qd = lane & 3;
    const int warp_m = (warp & 3) * 32;
    const int warp_n = (warp >> 2) * 64;
    const int m0 = blockIdx.y * 128;
    const int n0 = blockIdx.x * 128;

    const int a_r = tid >> 3;
    const int a_c = (tid & 7) << 2;
    const int b_r = tid >> 5;
    const int b_c = (tid & 31) << 2;

    const uint32_t as_u = (uint32_t)__cvta_generic_to_shared(As);
    const uint32_t bs_u = (uint32_t)__cvta_generic_to_shared(Bs);
    const uint32_t a_dst0 = as_u + ((uint32_t)(a_r*AS_STRIDE + a_c) << 2);
    const uint32_t b_dst0 = bs_u + ((uint32_t)(b_r*BS_STRIDE + b_c) << 2);

    const float* Ag0 = A + (size_t)(m0 + a_r)*lda + a_c;
    const float* Bg0 = B + (size_t)b_r*N + n0 + b_c;

    const int kTiles = K >> 5;

    #pragma unroll
    for (int s = 0; s < 2; s++) {
        if (s < kTiles) {
            const float* Ag = Ag0 + s*32;
            const float* Bg = Bg0 + (size_t)s*32*N;
            #pragma unroll
            for (int i = 0; i < 4; i++)
                cp16(a_dst0 + s*A_STG_BYTES + i*32*AS_STRIDE*4, Ag + (size_t)i*32*lda);
            #pragma unroll
            for (int i = 0; i < 4; i++)
                cp16(b_dst0 + s*B_STG_BYTES + i*8*BS_STRIDE*4, Bg + (size_t)i*8*N);
        }
        asm volatile("cp.async.commit_group;");
    }
    asm volatile("cp.async.wait_group 1;");
    __syncthreads();

    float acc[2][8][4];
    #pragma unroll
    for (int mt = 0; mt < 2; mt++)
        #pragma unroll
        for (int nt = 0; nt < 8; nt++)
            #pragma unroll
            for (int i = 0; i < 4; i++) acc[mt][nt][i] = 0.f;

    for (int t = 0; t < kTiles; t++) {
        const int stage = t & 1;
        const float* Acur = As + stage*128*AS_STRIDE;
        const float* Bcur = Bs + stage*32*BS_STRIDE;
        #pragma unroll
        for (int kk = 0; kk < 4; kk++) {
            const int k = kk*8;
            uint32_t af[2][4];
            #pragma unroll
            for (int mt = 0; mt < 2; mt++) {
                const int r0 = warp_m + mt*16 + gq;
                af[mt][0] = __float_as_uint(Acur[ r0    *AS_STRIDE + k + qd    ]);
                af[mt][1] = __float_as_uint(Acur[(r0+8) *AS_STRIDE + k + qd    ]);
                af[mt][2] = __float_as_uint(Acur[ r0    *AS_STRIDE + k + qd + 4]);
                af[mt][3] = __float_as_uint(Acur[(r0+8) *AS_STRIDE + k + qd + 4]);
            }
            #pragma unroll
            for (int nt = 0; nt < 8; nt++) {
                const int c = warp_n + nt*8 + gq;
                uint32_t b0 = __float_as_uint(Bcur[(k + qd    )*BS_STRIDE + c]);
                uint32_t b1 = __float_as_uint(Bcur[(k + qd + 4)*BS_STRIDE + c]);
                mma_tf32(acc[0][nt], af[0], b0, b1);
                mma_tf32(acc[1][nt], af[1], b0, b1);
            }
        }
        if (t + 1 < kTiles) {
            __syncthreads();
            if (t + 2 < kTiles) {
                const float* Ag = Ag0 + (t+2)*32;
                const float* Bg = Bg0 + (size_t)(t+2)*32*N;
                #pragma unroll
                for (int i = 0; i < 4; i++)
                    cp16(a_dst0 + stage*A_STG_BYTES + i*32*AS_STRIDE*4, Ag + (size_t)i*32*lda);
                #pragma unroll
                for (int i = 0; i < 4; i++)
                    cp16(b_dst0 + stage*B_STG_BYTES + i*8*BS_STRIDE*4, Bg + (size_t)i*8*N);
            }
            asm volatile("cp.async.commit_group;");
            asm volatile("cp.async.wait_group 1;");
            __syncthreads();
        }
    }

    const bool gelu_tile = (MODE == 1) && (n0 >= 1536);
    #pragma unroll
    for (int mt = 0; mt < 2; mt++) {
        const int r0 = m0 + warp_m + mt*16 + gq;
        #pragma unroll
        for (int nt = 0; nt < 8; nt++) {
            const int c = n0 + warp_n + nt*8 + 2*qd;
            if (MODE == 1) {
                if (gelu_tile) {
                    #pragma unroll
                    for (int hh = 0; hh < 2; hh++) {
                        int rr = r0 + hh*8;
                        float v0 = acc[mt][nt][hh*2+0], v1 = acc[mt][nt][hh*2+1];
                        float gl0 = 0.5f*v0*(1.f + erff(v0*0.70710678118654752f));
                        float gl1 = 0.5f*v1*(1.f + erff(v1*0.70710678118654752f));
                        *(float2*)&g_cat[(size_t)rr*VP + (c - 1024)] =
                            make_float2(f2tf32(gl0), f2tf32(gl1));
                    }
                } else {
                    #pragma unroll
                    for (int hh = 0; hh < 2; hh++) {
                        int rr = r0 + hh*8;
                        *(float2*)&C[(size_t)rr*N + c] =
                            make_float2(f2tf32(acc[mt][nt][hh*2+0]), f2tf32(acc[mt][nt][hh*2+1]));
                    }
                }
            } else {
                *(float2*)&C[(size_t)r0    *N + c] = make_float2(acc[mt][nt][0], acc[mt][nt][1]);
                *(float2*)&C[(size_t)(r0+8)*N + c] = make_float2(acc[mt][nt][2], acc[mt][nt][3]);
            }
        }
    }
}

// ---------------- split-K reduce + bias ----------------
__global__ void reduce_kernel(float* __restrict__ out, const float* __restrict__ bias)
{
    int i = blockIdx.x*256 + threadIdx.x;
    if (i >= ROWS*HIDDEN/4) return;
    size_t off = (size_t)i*4;
    const size_t stride = (size_t)ROWS*HIDDEN;
    float4 a = *(const float4*)&g_part[off];
    float4 b = *(const float4*)&g_part[off + stride];
    float4 c = *(const float4*)&g_part[off + 2*stride];
    float4 d = *(const float4*)&g_part[off + 3*stride];
    int col = (int)(off & (HIDDEN-1));
    float4 bb = *(const float4*)&bias[col];
    float4 r;
    r.x = a.x + b.x + c.x + d.x + bb.x;
    r.y = a.y + b.y + c.y + d.y + bb.y;
    r.z = a.z + b.z + c.z + d.z + bb.z;
    r.w = a.w + b.w + c.w + d.w + bb.w;
    *(float4*)&out[off] = r;
}

// ---------------- flash attention: split-K (flash-decoding) -------------------
// grid (chunk=4, qb=32, bh=16); each CTA handles <= CHUNK_TILES K-tiles.
// nc==1 -> direct g_cat write; else unnormalized partials to g_part/g_ml.
#define KST 68
#define VST 72
#define STG_FLOATS (64*KST + 64*VST)
__global__ void __launch_bounds__(128, 3) attn_mma_kernel()
{
    const int qb    = blockIdx.y;
    const int ntiles = qb + 1;
    const int chunk = blockIdx.x;
    const int start = chunk*CHUNK_TILES;
    if (start >= ntiles) return;
    const int end   = min(start + CHUNK_TILES, ntiles);
    const int nc    = (ntiles + CHUNK_TILES - 1) / CHUNK_TILES;

    extern __shared__ float smem[];
    float* stg[2] = { smem, smem + STG_FLOATS };

    const int bz = blockIdx.z;          // b*HEADS + h
    const int h  = bz & 7;
    const int b  = bz >> 3;
    const int q0 = qb*64;
    const int tid  = threadIdx.x;
    const int warp = tid >> 5;
    const int lane = tid & 31;
    const int gq = lane >> 2;
    const int qd = lane & 3;

    const float scale = 0.125f;
    const float slope = exp2f(-(float)(h+1));

    const uint32_t s_u[2] = { (uint32_t)__cvta_generic_to_shared(stg[0]),
                              (uint32_t)__cvta_generic_to_shared(stg[1]) };
    const int chunk_r = tid >> 4;
    const int chunk_c = (tid & 15) << 2;

    const int nt_loc = end - start;

    // ---- group A: Q -> stage1 K region, first tile K/V -> stage0
    {
        const float* qbase = g_proj + (size_t)(b*SEQ + q0 + chunk_r)*QKVP + h*HD + chunk_c;
        #pragma unroll
        for (int i = 0; i < 8; i++)
            cp16(s_u[1] + (((chunk_r + i*8)*KST + chunk_c) << 2), qbase + (size_t)i*8*QKVP);
        const float* kvb = g_proj + (size_t)(b*SEQ + start*64 + chunk_r)*QKVP + h*HD + chunk_c;
        #pragma unroll
        for (int i = 0; i < 8; i++) {
            cp16(s_u[0] + (((chunk_r + i*8)*KST + chunk_c) << 2),            kvb + (size_t)i*8*QKVP + 512);
            cp16(s_u[0] + ((64*KST + (chunk_r + i*8)*VST + chunk_c) << 2),   kvb + (size_t)i*8*QKVP + 1024);
        }
        asm volatile("cp.async.commit_group;");
    }
    asm volatile("cp.async.wait_group 0;");
    __syncthreads();

    uint32_t qf[8][4];
    {
        const float* Qs = stg[1];
        int r0 = warp*16 + gq;
        #pragma unroll
        for (int kt = 0; kt < 8; kt++) {
            int k0 = kt*8;
            qf[kt][0] = __float_as_uint(Qs[ r0     *KST + k0 + qd    ]);
            qf[kt][1] = __float_as_uint(Qs[(r0+8)  *KST + k0 + qd    ]);
            qf[kt][2] = __float_as_uint(Qs[ r0     *KST + k0 + qd + 4]);
            qf[kt][3] = __float_as_uint(Qs[(r0+8)  *KST + k0 + qd + 4]);
        }
    }
    __syncthreads();

    if (nt_loc > 1) {
        const float* kvb = g_proj + (size_t)(b*SEQ + (start+1)*64 + chunk_r)*QKVP + h*HD + chunk_c;
        #pragma unroll
        for (int i = 0; i < 8; i++) {
            cp16(s_u[1] + (((chunk_r + i*8)*KST + chunk_c) << 2),          kvb + (size_t)i*8*QKVP + 512);
            cp16(s_u[1] + ((64*KST + (chunk_r + i*8)*VST + chunk_c) << 2), kvb + (size_t)i*8*QKVP + 1024);
        }
        asm volatile("cp.async.commit_group;");
    }

    float o[8][4];
    #pragma unroll
    for (int t = 0; t < 8; t++) { o[t][0]=0.f; o[t][1]=0.f; o[t][2]=0.f; o[t][3]=0.f; }
    float m0 = -INFINITY, m1 = -INFINITY, l0 = 0.f, l1 = 0.f;
    const int i0 = q0 + warp*16 + gq;
    const int i1 = i0 + 8;
    const int prow0 = (warp*16 + gq)*KST;
    const int prow1 = (warp*16 + gq + 8)*KST;

    for (int lt = 0; lt < nt_loc; lt++) {
        const int jt = start + lt;
        const int j0 = jt*64;
        const int st = lt & 1;
        float* Ks = stg[st];
        const float* Vs = stg[st] + 64*KST;

        float s[8][4];
        #pragma unroll
        for (int t = 0; t < 8; t++) { s[t][0]=0.f; s[t][1]=0.f; s[t][2]=0.f; s[t][3]=0.f; }
        #pragma unroll
        for (int kt = 0; kt < 8; kt++) {
            int k0 = kt*8;
            #pragma unroll
            for (int nt = 0; nt < 8; nt++) {
                int n0 = nt*8;
                uint32_t b0 = __float_as_uint(Ks[(n0+gq)*KST + k0 + qd    ]);
                uint32_t b1 = __float_as_uint(Ks[(n0+gq)*KST + k0 + qd + 4]);
                mma_tf32(s[nt], qf[kt], b0, b1);
            }
        }

        float rm0 = -INFINITY, rm1 = -INFINITY;
        #pragma unroll
        for (int nt = 0; nt < 8; nt++) {
            int j = j0 + nt*8 + 2*qd;
            s[nt][0] = (j   <= i0) ? fmaf(s[nt][0], scale, slope*(float)j    ) : -1e30f;
            s[nt][1] = (j+1 <= i0) ? fmaf(s[nt][1], scale, slope*(float)(j+1)) : -1e30f;
            s[nt][2] = (j   <= i1) ? fmaf(s[nt][2], scale, slope*(float)j    ) : -1e30f;
            s[nt][3] = (j+1 <= i1) ? fmaf(s[nt][3], scale, slope*(float)(j+1)) : -1e30f;
            rm0 = fmaxf(rm0, fmaxf(s[nt][0], s[nt][1]));
            rm1 = fmaxf(rm1, fmaxf(s[nt][2], s[nt][3]));
        }
        rm0 = fmaxf(rm0, __shfl_xor_sync(0xffffffffu, rm0, 1));
        rm0 = fmaxf(rm0, __shfl_xor_sync(0xffffffffu, rm0, 2));
        rm1 = fmaxf(rm1, __shfl_xor_sync(0xffffffffu, rm1, 1));
        rm1 = fmaxf(rm1, __shfl_xor_sync(0xffffffffu, rm1, 2));
        float nm0 = fmaxf(m0, rm0), nm1 = fmaxf(m1, rm1);
        float c0 = __expf(m0 - nm0), c1 = __expf(m1 - nm1);
        m0 = nm0; m1 = nm1;
        float pv[8][4];
        float ps0 = 0.f, ps1 = 0.f;
        #pragma unroll
        for (int nt = 0; nt < 8; nt++) {
            pv[nt][0] = __expf(s[nt][0] - nm0);
            pv[nt][1] = __expf(s[nt][1] - nm0);
            pv[nt][2] = __expf(s[nt][2] - nm1);
            pv[nt][3] = __expf(s[nt][3] - nm1);
            ps0 += pv[nt][0] + pv[nt][1];
            ps1 += pv[nt][2] + pv[nt][3];
            o[nt][0] *= c0; o[nt][1] *= c0; o[nt][2] *= c1; o[nt][3] *= c1;
        }
        ps0 += __shfl_xor_sync(0xffffffffu, ps0, 1);
        ps0 += __shfl_xor_sync(0xffffffffu, ps0, 2);
        ps1 += __shfl_xor_sync(0xffffffffu, ps1, 1);
        ps1 += __shfl_xor_sync(0xffffffffu, ps1, 2);
        l0 = l0*c0 + ps0;
        l1 = l1*c1 + ps1;

        __syncthreads();                     // all warps done reading K -> reuse as P
        #pragma unroll
        for (int nt = 0; nt < 8; nt++) {
            int cl = nt*8 + 2*qd;
            *(float2*)&Ks[prow0 + cl] = make_float2(f2tf32(pv[nt][0]), f2tf32(pv[nt][1]));
            *(float2*)&Ks[prow1 + cl] = make_float2(f2tf32(pv[nt][2]), f2tf32(pv[nt][3]));
        }
        __syncwarp();

        #pragma unroll
        for (int kt = 0; kt < 8; kt++) {
            int k0 = kt*8;
            uint32_t pa[4];
            pa[0] = __float_as_uint(Ks[prow0 + k0 + qd    ]);
            pa[1] = __float_as_uint(Ks[prow1 + k0 + qd    ]);
            pa[2] = __float_as_uint(Ks[prow0 + k0 + qd + 4]);
            pa[3] = __float_as_uint(Ks[prow1 + k0 + qd + 4]);
            #pragma unroll
            for (int nt = 0; nt < 8; nt++) {
                int n0 = nt*8;
                uint32_t b0 = __float_as_uint(Vs[(k0+qd  )*VST + n0 + gq]);
                uint32_t b1 = __float_as_uint(Vs[(k0+qd+4)*VST + n0 + gq]);
                mma_tf32(o[nt], pa, b0, b1);
            }
        }
        __syncthreads();

        if (lt + 1 < nt_loc) {
            if (lt + 2 < nt_loc) {
                const int jn = (start + lt + 2)*64;
                const float* kvb = g_proj + (size_t)(b*SEQ + jn + chunk_r)*QKVP + h*HD + chunk_c;
                #pragma unroll
                for (int i = 0; i < 8; i++) {
                    cp16(s_u[st] + (((chunk_r + i*8)*KST + chunk_c) << 2),          kvb + (size_t)i*8*QKVP + 512);
                    cp16(s_u[st] + ((64*KST + (chunk_r + i*8)*VST + chunk_c) << 2), kvb + (size_t)i*8*QKVP + 1024);
                }
            }
            asm volatile("cp.async.commit_group;");
            asm volatile("cp.async.wait_group 1;");
            __syncthreads();
        }
    }

    if (nc == 1) {
        // direct finalize
        float inv0 = 1.f / l0, inv1 = 1.f / l1;
        size_t ob0 = (size_t)(b*SEQ + i0)*VP + h*HD;
        size_t ob1 = (size_t)(b*SEQ + i1)*VP + h*HD;
        #pragma unroll
        for (int nt = 0; nt < 8; nt++) {
            int cl = nt*8 + 2*qd;
            *(float2*)&g_cat[ob0 + cl] = make_float2(f2tf32(o[nt][0]*inv0), f2tf32(o[nt][1]*inv0));
            *(float2*)&g_cat[ob1 + cl] = make_float2(f2tf32(o[nt][2]*inv1), f2tf32(o[nt][3]*inv1));
        }
    } else {
        // partials: O unnormalized + (m,l)
        const int pb = (bz*32 + qb)*4 + chunk;
        float* po = g_part + (size_t)pb*4096;
        const int r0 = warp*16 + gq;
        const int r1 = r0 + 8;
        #pragma unroll
        for (int nt = 0; nt < 8; nt++) {
            int cl = nt*8 + 2*qd;
            *(float2*)&po[r0*64 + cl] = make_float2(o[nt][0], o[nt][1]);
            *(float2*)&po[r1*64 + cl] = make_float2(o[nt][2], o[nt][3]);
        }
        if (qd == 0) {
            float* ml = g_ml + (size_t)pb*128;
            ml[r0] = m0;  ml[64 + r0] = l0;
            ml[r1] = m1;  ml[64 + r1] = l1;
        }
    }
}

// ---------------- attention combine (qb >= 8 only) ----------------
__global__ void __launch_bounds__(256) attn_combine_kernel()
{
    const int qb = 8 + blockIdx.x;        // 8..31
    const int bz = blockIdx.y;            // b*HEADS + h
    const int h  = bz & 7;
    const int b  = bz >> 3;
    const int nc = qb/CHUNK_TILES + 1;    // 2..4
    const int tid = threadIdx.x;
    const int row = tid >> 2;             // 0..63
    const int dg  = (tid & 3) << 4;       // 0,16,32,48

    const int pb0 = (bz*32 + qb)*4;
    float mc[4], lc[4];
    float M = -INFINITY;
    for (int c = 0; c < nc; c++) {
        const float* ml = g_ml + (size_t)(pb0 + c)*128;
        mc[c] = ml[row];
        lc[c] = ml[64 + row];
        M = fmaxf(M, mc[c]);
    }
    float L = 0.f;
    float acc[16];
    #pragma unroll
    for (int i = 0; i < 16; i++) acc[i] = 0.f;
    for (int c = 0; c < nc; c++) {
        float w = __expf(mc[c] - M);
        L += lc[c]*w;
        const float* po = g_part + (size_t)(pb0 + c)*4096 + row*64 + dg;
        #pragma unroll
        for (int i = 0; i < 4; i++) {
            float4 v = *(const float4*)&po[i*4];
            acc[i*4+0] += v.x*w; acc[i*4+1] += v.y*w;
            acc[i*4+2] += v.z*w; acc[i*4+3] += v.w*w;
        }
    }
    float inv = 1.f / L;
    float* dst = g_cat + (size_t)(b*SEQ + qb*64 + row)*VP + h*HD + dg;
    #pragma unroll
    for (int i = 0; i < 4; i++) {
        float4 r;
        r.x = f2tf32(acc[i*4+0]*inv); r.y = f2tf32(acc[i*4+1]*inv);
        r.z = f2tf32(acc[i*4+2]*inv); r.w = f2tf32(acc[i*4+3]*inv);
        *(float4*)&dst[i*4] = r;
    }
}

// ---------------- launch ----------------
extern "C" void kernel_launch(void* const* d_in, const int* in_sizes, int n_in,
                              void* d_out, int out_size)
{
    (void)in_sizes; (void)n_in; (void)out_size;
    const float* x     = (const float*)d_in[0];
    const float* gamma = (const float*)d_in[1];
    const float* beta  = (const float*)d_in[2];
    const float* w_in  = (const float*)d_in[3];
    const float* w_out = (const float*)d_in[4];
    const float* b_out = (const float*)d_in[5];
    float* out = (float*)d_out;

    float *p_xt, *p_cat, *p_proj, *p_w1, *p_w2, *p_part;
    cudaGetSymbolAddress((void**)&p_xt,   g_xt);
    cudaGetSymbolAddress((void**)&p_proj, g_proj);
    cudaGetSymbolAddress((void**)&p_cat,  g_cat);
    cudaGetSymbolAddress((void**)&p_w1,   g_w1);
    cudaGetSymbolAddress((void**)&p_w2,   g_w2);
    cudaGetSymbolAddress((void**)&p_part, g_part);

    cvt_kernel<<<(HIDDEN*QKVP/4 + 255)/256, 256>>>(w_in,  p_w1, HIDDEN*QKVP);
    cvt_kernel<<<(VP*HIDDEN/4   + 255)/256, 256>>>(w_out, p_w2, VP*HIDDEN);

    ln_kernel<<<ROWS, 128>>>(x, gamma, beta);
    feat_kernel<<<(ROWS*128 + 255)/256, 256>>>();
    scan_kernel<<<BATCH*64, 256>>>();

    int gemm_smem = (2*128*AS_STRIDE + 2*32*BS_STRIDE) * sizeof(float);   // 71680
    cudaFuncSetAttribute(tgemm_kernel<1>, cudaFuncAttributeMaxDynamicSharedMemorySize, gemm_smem);
    cudaFuncSetAttribute(tgemm_kernel<2>, cudaFuncAttributeMaxDynamicSharedMemorySize, gemm_smem);

    dim3 g1(QKVP/128, ROWS/128);     // (28, 32) — gelu fused for cols >= 1536
    tgemm_kernel<1><<<g1, 256, gemm_smem>>>(p_xt, p_w1, p_proj, ROWS, QKVP, HIDDEN, HIDDEN);

    int attn_smem = 2*STG_FLOATS*sizeof(float);                           // 71680
    cudaFuncSetAttribute(attn_mma_kernel, cudaFuncAttributeMaxDynamicSharedMemorySize, attn_smem);
    attn_mma_kernel<<<dim3(4, SEQ/64, BATCH*HEADS), 128, attn_smem>>>();
    attn_combine_kernel<<<dim3(24, BATCH*HEADS), 256>>>();

    dim3 g2(HIDDEN/128, ROWS/128, KSPLITS);   // (4, 32, 4) split-K
    tgemm_kernel<2><<<g2, 256, gemm_smem>>>(p_cat, p_w2, p_part, ROWS, HIDDEN, KSPLIT, VP);
    reduce_kernel<<<(ROWS*HIDDEN/4 + 255)/256, 256>>>(out, b_out);
}

// round 8
// speedup vs baseline: 9.8226x; 1.5495x over previous
#include <cuda_runtime.h>
#include <cuda_fp16.h>
#include <math.h>
#include <stdint.h>

#define BATCH  2
#define SEQ    2048
#define ROWS   (BATCH*SEQ)     // 4096
#define HIDDEN 512
#define QKVP   3584
#define VP     2560
#define HEADS  8
#define HD     64
#define KSPLITS 4
#define KSPLIT  (VP/KSPLITS)   // 640
#define CHUNK_TILES 8

// ---------------- scratch ----------------
__device__ float  g_xn[(size_t)ROWS*HIDDEN];
__device__ __align__(128) __half g_xth [(size_t)ROWS*HIDDEN];
__device__ __align__(128) __half g_projh[(size_t)ROWS*1536];     // q,k,v
__device__ __align__(128) __half g_cath[(size_t)ROWS*VP];
__device__ __align__(128) __half g_w1t[(size_t)QKVP*HIDDEN];     // [N][K]
__device__ __align__(128) __half g_w2t[(size_t)HIDDEN*VP];       // [N][K]
__device__ float  g_part[(size_t)KSPLITS*ROWS*HIDDEN];           // attn partials, then split-K partials
__device__ float  g_ml[(size_t)BATCH*HEADS*32*4*128];

// ---------------- helpers ----------------
__device__ __forceinline__ uint32_t h2u(float a, float b) {
    __half2 h = __float22half2_rn(make_float2(a, b));
    return *reinterpret_cast<uint32_t*>(&h);
}
__device__ __forceinline__ void mma_f16(float* d, const uint32_t* a, uint32_t b0, uint32_t b1) {
    asm volatile("mma.sync.aligned.m16n8k16.row.col.f32.f16.f16.f32 "
        "{%0,%1,%2,%3}, {%4,%5,%6,%7}, {%8,%9}, {%0,%1,%2,%3};"
        : "+f"(d[0]), "+f"(d[1]), "+f"(d[2]), "+f"(d[3])
        : "r"(a[0]), "r"(a[1]), "r"(a[2]), "r"(a[3]), "r"(b0), "r"(b1));
}
__device__ __forceinline__ void ldsm4(uint32_t* r, uint32_t a) {
    asm volatile("ldmatrix.sync.aligned.m8n8.x4.shared.b16 {%0,%1,%2,%3}, [%4];"
        : "=r"(r[0]), "=r"(r[1]), "=r"(r[2]), "=r"(r[3]) : "r"(a));
}
__device__ __forceinline__ void ldsm4t(uint32_t* r, uint32_t a) {
    asm volatile("ldmatrix.sync.aligned.m8n8.x4.trans.shared.b16 {%0,%1,%2,%3}, [%4];"
        : "=r"(r[0]), "=r"(r[1]), "=r"(r[2]), "=r"(r[3]) : "r"(a));
}
__device__ __forceinline__ void cp16(uint32_t dst, const void* src) {
    asm volatile("cp.async.cg.shared.global [%0], [%1], 16;" :: "r"(dst), "l"(src));
}

// ---------------- weight transpose + fp16 convert: [K][N] f32 -> [N][K] h ----
__global__ void __launch_bounds__(256) trans_cvt_kernel(
    const float* __restrict__ src, __half* __restrict__ dst, int K, int N)
{
    __shared__ __half t[32][33];
    int k0 = blockIdx.x*32, n0 = blockIdx.y*32;
    int tx = threadIdx.x & 31, ty = threadIdx.x >> 5;   // ty 0..7
    #pragma unroll
    for (int i = 0; i < 32; i += 8)
        t[ty+i][tx] = __float2half_rn(src[(size_t)(k0+ty+i)*N + n0+tx]);
    __syncthreads();
    #pragma unroll
    for (int i = 0; i < 32; i += 8)
        dst[(size_t)(n0+ty+i)*K + k0+tx] = t[tx][ty+i];
}

// ---------------- LayerNorm (+ fused ident feature copy) ----------------
__global__ void __launch_bounds__(128) ln_kernel(const float* __restrict__ x,
                                                 const float* __restrict__ gamma,
                                                 const float* __restrict__ beta)
{
    int row = blockIdx.x;
    int tid = threadIdx.x;
    const float* xr = x + (size_t)row*HIDDEN;
    float v[4];
    float s = 0.f;
    #pragma unroll
    for (int i = 0; i < 4; i++) { v[i] = xr[tid + i*128]; s += v[i]; }
    __shared__ float red[4];
    #pragma unroll
    for (int o = 16; o > 0; o >>= 1) s += __shfl_xor_sync(0xffffffffu, s, o);
    if ((tid & 31) == 0) red[tid >> 5] = s;
    __syncthreads();
    float mu = (red[0]+red[1]+red[2]+red[3]) * (1.f/HIDDEN);
    float vs = 0.f;
    #pragma unroll
    for (int i = 0; i < 4; i++) { float d = v[i]-mu; vs += d*d; }
    #pragma unroll
    for (int o = 16; o > 0; o >>= 1) vs += __shfl_xor_sync(0xffffffffu, vs, o);
    __syncthreads();
    if ((tid & 31) == 0) red[tid >> 5] = vs;
    __syncthreads();
    float var  = (red[0]+red[1]+red[2]+red[3]) * (1.f/HIDDEN);
    float rstd = rsqrtf(var + 1e-5f);
    #pragma unroll
    for (int i = 0; i < 4; i++) {
        int c = tid + i*128;
        float xn = (v[i]-mu)*rstd*gamma[c] + beta[c];
        g_xn[(size_t)row*HIDDEN + c] = xn;
        if (c < 320) g_xth[(size_t)row*HIDDEN + c] = __float2half_rn(xn);
    }
}

// ---------------- feature transform: shift channels ----------------
__global__ void feat_kernel()
{
    int idx = blockIdx.x*256 + threadIdx.x;
    if (idx >= ROWS*128) return;
    int c   = 384 + (idx & 127);
    int row = idx >> 7;
    int i   = row & (SEQ-1);
    size_t base = (size_t)row*HIDDEN + c;
    float val;
    if (c < 448)  val = (i >= 1) ? g_xn[base -   HIDDEN] : 0.f;
    else          val = (i >= 2) ? g_xn[base - 2*HIDDEN] : 0.f;
    g_xth[base] = __float2half_rn(val);
}

// ---------------- cumlogsumexp scan ----------------
__global__ void __launch_bounds__(256) scan_kernel()
{
    int bc  = blockIdx.x;
    int b   = bc >> 6;
    int ch  = 320 + (bc & 63);
    int tid = threadIdx.x;
    int row0 = b*SEQ + tid*8;
    float y[8];
    #pragma unroll
    for (int i = 0; i < 8; i++) y[i] = 5.f * g_xn[(size_t)(row0+i)*HIDDEN + ch];
    float m = -INFINITY, s = 0.f;
    #pragma unroll
    for (int i = 0; i < 8; i++) {
        float M = fmaxf(m, y[i]);
        s = s*expf(m - M) + expf(y[i] - M);
        m = M;
    }
    __shared__ float sm[256], ss[256];
    sm[tid] = m; ss[tid] = s;
    __syncthreads();
    for (int off = 1; off < 256; off <<= 1) {
        float pm = 0.f, ps = 0.f;
        bool act = (tid >= off);
        if (act) { pm = sm[tid-off]; ps = ss[tid-off]; }
        __syncthreads();
        if (act) {
            float M = fmaxf(pm, m);
            s = ps*expf(pm - M) + s*expf(m - M);
            m = M;
            sm[tid] = m; ss[tid] = s;
        }
        __syncthreads();
    }
    float pm = -INFINITY, ps = 0.f;
    if (tid > 0) { pm = sm[tid-1]; ps = ss[tid-1]; }
    #pragma unroll
    for (int i = 0; i < 8; i++) {
        float M = fmaxf(pm, y[i]);
        ps = ps*expf(pm - M) + expf(y[i] - M);
        pm = M;
        g_xth[(size_t)(row0+i)*HIDDEN + ch] = __float2half_rn((pm + logf(ps)) * 0.2f);
    }
}

// ---------------- fp16 tensor GEMM: 128x128 tile, BK=32, ldmatrix + mma.k16 ---
// A [M][K] h (K-contig), B [N][K] h (K-contig).
// MODE 1: c<1536 -> g_projh; c>=1536 -> gelu -> g_cath[.., c-1024]
// MODE 2: split-K partials (fp32) -> C + z*ROWS*N
#define AST 40                 // halves per row (80B: 5r mod 8 -> conflict-free ldsm)
#define ASTG (128*AST)         // halves per stage
template<int MODE>
__global__ void __launch_bounds__(256, 2) hgemm_kernel(
    const __half* __restrict__ A, const __half* __restrict__ B,
    float* __restrict__ C, int K, int lda, int ldb, int N)
{
    extern __shared__ __half hsm[];
    __half* As = hsm;                    // 2 x 128 x AST
    __half* Bs = hsm + 2*ASTG;

    if (MODE == 2) {
        const int z = blockIdx.z;
        A += (size_t)z*K;
        B += (size_t)z*K;
        C += (size_t)z*ROWS*N;
    }

    const int tid  = threadIdx.x;
    const int warp = tid >> 5;
    const int lane = tid & 31;
    const int gq = lane >> 2;
    const int qd = lane & 3;
    const int warp_m = (warp & 3) * 32;
    const int warp_n = (warp >> 2) * 64;
    const int m0 = blockIdx.y * 128;
    const int n0 = blockIdx.x * 128;
    const int lrow  = lane & 15;
    const int lcol8 = (lane >> 4) * 8;

    const int a_r  = tid >> 2;           // 0..63 (+64 second pass)
    const int a_c8 = (tid & 3) * 8;

    const uint32_t as_u = (uint32_t)__cvta_generic_to_shared(As);
    const uint32_t bs_u = (uint32_t)__cvta_generic_to_shared(Bs);
    const uint32_t a_dst0 = as_u + (uint32_t)(a_r*AST + a_c8)*2;
    const uint32_t b_dst0 = bs_u + (uint32_t)(a_r*AST + a_c8)*2;

    const __half* Ag0 = A + (size_t)(m0 + a_r)*lda + a_c8;
    const __half* Bg0 = B + (size_t)(n0 + a_r)*ldb + a_c8;

    const int kTiles = K >> 5;

    #pragma unroll
    for (int s = 0; s < 2; s++) {
        if (s < kTiles) {
            const __half* Ag = Ag0 + s*32;
            const __half* Bg = Bg0 + s*32;
            #pragma unroll
            for (int i = 0; i < 2; i++) {
                cp16(a_dst0 + (uint32_t)(s*ASTG + i*64*AST)*2, Ag + (size_t)i*64*lda);
                cp16(b_dst0 + (uint32_t)(s*ASTG + i*64*AST)*2, Bg + (size_t)i*64*ldb);
            }
        }
        asm volatile("cp.async.commit_group;");
    }
    asm volatile("cp.async.wait_group 1;");
    __syncthreads();

    float acc[2][8][4];
    #pragma unroll
    for (int mt = 0; mt < 2; mt++)
        #pragma unroll
        for (int nt = 0; nt < 8; nt++)
            #pragma unroll
            for (int i = 0; i < 4; i++) acc[mt][nt][i] = 0.f;

    for (int t = 0; t < kTiles; t++) {
        const int stage = t & 1;
        const uint32_t asb = as_u + (uint32_t)(stage*ASTG)*2;
        const uint32_t bsb = bs_u + (uint32_t)(stage*ASTG)*2;
        #pragma unroll
        for (int kk = 0; kk < 2; kk++) {
            uint32_t af[2][4];
            #pragma unroll
            for (int mt = 0; mt < 2; mt++)
                ldsm4(af[mt], asb + (uint32_t)((warp_m + mt*16 + lrow)*AST + kk*16 + lcol8)*2);
            #pragma unroll
            for (int p = 0; p < 4; p++) {
                uint32_t bf[4];
                ldsm4(bf, bsb + (uint32_t)((warp_n + p*16 + lrow)*AST + kk*16 + lcol8)*2);
                mma_f16(acc[0][2*p],   af[0], bf[0], bf[2]);
                mma_f16(acc[0][2*p+1], af[0], bf[1], bf[3]);
                mma_f16(acc[1][2*p],   af[1], bf[0], bf[2]);
                mma_f16(acc[1][2*p+1], af[1], bf[1], bf[3]);
            }
        }
        if (t + 1 < kTiles) {
            __syncthreads();
            if (t + 2 < kTiles) {
                const __half* Ag = Ag0 + (t+2)*32;
                const __half* Bg = Bg0 + (t+2)*32;
                #pragma unroll
                for (int i = 0; i < 2; i++) {
                    cp16(a_dst0 + (uint32_t)(stage*ASTG + i*64*AST)*2, Ag + (size_t)i*64*lda);
                    cp16(b_dst0 + (uint32_t)(stage*ASTG + i*64*AST)*2, Bg + (size_t)i*64*ldb);
                }
            }
            asm volatile("cp.async.commit_group;");
            asm volatile("cp.async.wait_group 1;");
            __syncthreads();
        }
    }

    #pragma unroll
    for (int mt = 0; mt < 2; mt++) {
        const int r0 = m0 + warp_m + mt*16 + gq;
        #pragma unroll
        for (int nt = 0; nt < 8; nt++) {
            const int c = n0 + warp_n + nt*8 + 2*qd;
            if (MODE == 1) {
                if (c >= 1536) {
                    #pragma unroll
                    for (int hh = 0; hh < 2; hh++) {
                        int rr = r0 + hh*8;
                        float v0 = acc[mt][nt][hh*2+0], v1 = acc[mt][nt][hh*2+1];
                        float gl0 = 0.5f*v0*(1.f + erff(v0*0.70710678118654752f));
                        float gl1 = 0.5f*v1*(1.f + erff(v1*0.70710678118654752f));
                        *(__half2*)&g_cath[(size_t)rr*VP + (c - 1024)] =
                            __float22half2_rn(make_float2(gl0, gl1));
                    }
                } else {
                    #pragma unroll
                    for (int hh = 0; hh < 2; hh++) {
                        int rr = r0 + hh*8;
                        *(__half2*)&g_projh[(size_t)rr*1536 + c] =
                            __float22half2_rn(make_float2(acc[mt][nt][hh*2+0], acc[mt][nt][hh*2+1]));
                    }
                }
            } else {
                *(float2*)&C[(size_t)r0    *N + c] = make_float2(acc[mt][nt][0], acc[mt][nt][1]);
                *(float2*)&C[(size_t)(r0+8)*N + c] = make_float2(acc[mt][nt][2], acc[mt][nt][3]);
            }
        }
    }
}

// ---------------- split-K reduce + bias ----------------
__global__ void reduce_kernel(float* __restrict__ out, const float* __restrict__ bias)
{
    int i = blockIdx.x*256 + threadIdx.x;
    if (i >= ROWS*HIDDEN/4) return;
    size_t off = (size_t)i*4;
    const size_t stride = (size_t)ROWS*HIDDEN;
    float4 a = *(const float4*)&g_part[off];
    float4 b = *(const float4*)&g_part[off + stride];
    float4 c = *(const float4*)&g_part[off + 2*stride];
    float4 d = *(const float4*)&g_part[off + 3*stride];
    int col = (int)(off & (HIDDEN-1));
    float4 bb = *(const float4*)&bias[col];
    float4 r;
    r.x = a.x + b.x + c.x + d.x + bb.x;
    r.y = a.y + b.y + c.y + d.y + bb.y;
    r.z = a.z + b.z + c.z + d.z + bb.z;
    r.w = a.w + b.w + c.w + d.w + bb.w;
    *(float4*)&out[off] = r;
}

// ---------------- flash attention: fp16 mma, split-K, P-in-registers ----------
#define QST 72                 // halves (144B: 9r mod 8 -> conflict-free ldsm)
#define QTILE (64*QST)         // halves per 64-row tile
__global__ void __launch_bounds__(128, 4) attn_mma_kernel()
{
    const int qb     = blockIdx.y;
    const int ntiles = qb + 1;
    const int chunk  = blockIdx.x;
    const int start  = chunk*CHUNK_TILES;
    if (start >= ntiles) return;
    const int end    = min(start + CHUNK_TILES, ntiles);
    const int nc     = (ntiles + CHUNK_TILES - 1) / CHUNK_TILES;
    const int nt_loc = end - start;

    extern __shared__ __half asm_[];
    __half* Qs = asm_;                                  // 64 x QST
    // stage s: K at QTILE + s*2*QTILE, V at +QTILE
    const int bz = blockIdx.z;
    const int h  = bz & 7;
    const int b  = bz >> 3;
    const int q0 = qb*64;
    const int tid  = threadIdx.x;
    const int warp = tid >> 5;
    const int lane = tid & 31;
    const int gq = lane >> 2;
    const int qd = lane & 3;
    const int lrow  = lane & 15;
    const int lcol8 = (lane >> 4) * 8;
    const int vrow  = (lane & 7) + ((lane >> 3) & 1) * 8;

    const float scale = 0.125f;
    const float slope = exp2f(-(float)(h+1));

    const uint32_t q_u = (uint32_t)__cvta_generic_to_shared(Qs);
    const uint32_t k_u[2] = { q_u + (uint32_t)QTILE*2, q_u + (uint32_t)(3*QTILE)*2 };
    const uint32_t v_u[2] = { q_u + (uint32_t)(2*QTILE)*2, q_u + (uint32_t)(4*QTILE)*2 };

    const int cr  = tid >> 3;            // 0..15
    const int cc8 = (tid & 7) * 8;       // halves

    // ---- group A: Q + tile start K/V
    {
        const __half* qb_ = g_projh + (size_t)(b*SEQ + q0 + cr)*1536 + h*HD + cc8;
        #pragma unroll
        for (int i = 0; i < 4; i++)
            cp16(q_u + (uint32_t)((cr + i*16)*QST + cc8)*2, qb_ + (size_t)i*16*1536);
        const __half* kv = g_projh + (size_t)(b*SEQ + start*64 + cr)*1536 + h*HD + cc8;
        #pragma unroll
        for (int i = 0; i < 4; i++) {
            cp16(k_u[0] + (uint32_t)((cr + i*16)*QST + cc8)*2, kv + (size_t)i*16*1536 + 512);
            cp16(v_u[0] + (uint32_t)((cr + i*16)*QST + cc8)*2, kv + (size_t)i*16*1536 + 1024);
        }
        asm volatile("cp.async.commit_group;");
    }
    // ---- group B: next tile
    if (nt_loc > 1) {
        const __half* kv = g_projh + (size_t)(b*SEQ + (start+1)*64 + cr)*1536 + h*HD + cc8;
        #pragma unroll
        for (int i = 0; i < 4; i++) {
            cp16(k_u[1] + (uint32_t)((cr + i*16)*QST + cc8)*2, kv + (size_t)i*16*1536 + 512);
            cp16(v_u[1] + (uint32_t)((cr + i*16)*QST + cc8)*2, kv + (size_t)i*16*1536 + 1024);
        }
    }
    asm volatile("cp.async.commit_group;");
    asm volatile("cp.async.wait_group 1;");   // Q + tile0 ready
    __syncthreads();

    // ---- Q fragments
    uint32_t qf[4][4];
    #pragma unroll
    for (int kt = 0; kt < 4; kt++)
        ldsm4(qf[kt], q_u + (uint32_t)((warp*16 + lrow)*QST + kt*16 + lcol8)*2);

    float o[8][4];
    #pragma unroll
    for (int t = 0; t < 8; t++) { o[t][0]=0.f; o[t][1]=0.f; o[t][2]=0.f; o[t][3]=0.f; }
    float m0 = -INFINITY, m1 = -INFINITY, l0 = 0.f, l1 = 0.f;
    const int i0 = q0 + warp*16 + gq;
    const int i1 = i0 + 8;

    for (int lt = 0; lt < nt_loc; lt++) {
        const int j0 = (start + lt)*64;
        const int st = lt & 1;

        // ---- S = Q @ K^T
        float s[8][4];
        #pragma unroll
        for (int t = 0; t < 8; t++) { s[t][0]=0.f; s[t][1]=0.f; s[t][2]=0.f; s[t][3]=0.f; }
        #pragma unroll
        for (int kt = 0; kt < 4; kt++) {
            #pragma unroll
            for (int p = 0; p < 4; p++) {
                uint32_t bf[4];
                ldsm4(bf, k_u[st] + (uint32_t)((p*16 + lrow)*QST + kt*16 + lcol8)*2);
                mma_f16(s[2*p],   qf[kt], bf[0], bf[2]);
                mma_f16(s[2*p+1], qf[kt], bf[1], bf[3]);
            }
        }

        // ---- mask/scale/alibi + online softmax
        float rm0 = -INFINITY, rm1 = -INFINITY;
        #pragma unroll
        for (int nt = 0; nt < 8; nt++) {
            int j = j0 + nt*8 + 2*qd;
            s[nt][0] = (j   <= i0) ? fmaf(s[nt][0], scale, slope*(float)j    ) : -1e30f;
            s[nt][1] = (j+1 <= i0) ? fmaf(s[nt][1], scale, slope*(float)(j+1)) : -1e30f;
            s[nt][2] = (j   <= i1) ? fmaf(s[nt][2], scale, slope*(float)j    ) : -1e30f;
            s[nt][3] = (j+1 <= i1) ? fmaf(s[nt][3], scale, slope*(float)(j+1)) : -1e30f;
            rm0 = fmaxf(rm0, fmaxf(s[nt][0], s[nt][1]));
            rm1 = fmaxf(rm1, fmaxf(s[nt][2], s[nt][3]));
        }
        rm0 = fmaxf(rm0, __shfl_xor_sync(0xffffffffu, rm0, 1));
        rm0 = fmaxf(rm0, __shfl_xor_sync(0xffffffffu, rm0, 2));
        rm1 = fmaxf(rm1, __shfl_xor_sync(0xffffffffu, rm1, 1));
        rm1 = fmaxf(rm1, __shfl_xor_sync(0xffffffffu, rm1, 2));
        float nm0 = fmaxf(m0, rm0), nm1 = fmaxf(m1, rm1);
        float c0 = __expf(m0 - nm0), c1 = __expf(m1 - nm1);
        m0 = nm0; m1 = nm1;
        float ps0 = 0.f, ps1 = 0.f;
        #pragma unroll
        for (int nt = 0; nt < 8; nt++) {
            s[nt][0] = __expf(s[nt][0] - nm0);
            s[nt][1] = __expf(s[nt][1] - nm0);
            s[nt][2] = __expf(s[nt][2] - nm1);
            s[nt][3] = __expf(s[nt][3] - nm1);
            ps0 += s[nt][0] + s[nt][1];
            ps1 += s[nt][2] + s[nt][3];
            o[nt][0] *= c0; o[nt][1] *= c0; o[nt][2] *= c1; o[nt][3] *= c1;
        }
        ps0 += __shfl_xor_sync(0xffffffffu, ps0, 1);
        ps0 += __shfl_xor_sync(0xffffffffu, ps0, 2);
        ps1 += __shfl_xor_sync(0xffffffffu, ps1, 1);
        ps1 += __shfl_xor_sync(0xffffffffu, ps1, 2);
        l0 = l0*c0 + ps0;
        l1 = l1*c1 + ps1;

        // ---- O += P @ V   (P straight from registers: C-frag == A-frag layout)
        #pragma unroll
        for (int c = 0; c < 4; c++) {       // j chunk of 16
            uint32_t pa[4];
            pa[0] = h2u(s[2*c][0],   s[2*c][1]);
            pa[1] = h2u(s[2*c][2],   s[2*c][3]);
            pa[2] = h2u(s[2*c+1][0], s[2*c+1][1]);
            pa[3] = h2u(s[2*c+1][2], s[2*c+1][3]);
            #pragma unroll
            for (int p = 0; p < 4; p++) {   // d chunk of 16
                uint32_t bf[4];
                ldsm4t(bf, v_u[st] + (uint32_t)((c*16 + vrow)*QST + p*16 + lcol8)*2);
                mma_f16(o[2*p],   pa, bf[0], bf[1]);
                mma_f16(o[2*p+1], pa, bf[2], bf[3]);
            }
        }
        __syncthreads();                    // all warps done with stage st

        if (lt + 1 < nt_loc) {
            if (lt + 2 < nt_loc) {
                const int jn = (start + lt + 2)*64;
                const __half* kv = g_projh + (size_t)(b*SEQ + jn + cr)*1536 + h*HD + cc8;
                #pragma unroll
                for (int i = 0; i < 4; i++) {
                    cp16(k_u[st] + (uint32_t)((cr + i*16)*QST + cc8)*2, kv + (size_t)i*16*1536 + 512);
                    cp16(v_u[st] + (uint32_t)((cr + i*16)*QST + cc8)*2, kv + (size_t)i*16*1536 + 1024);
                }
            }
            asm volatile("cp.async.commit_group;");
            asm volatile("cp.async.wait_group 1;");
            __syncthreads();
        }
    }

    if (nc == 1) {
        float inv0 = 1.f / l0, inv1 = 1.f / l1;
        size_t ob0 = (size_t)(b*SEQ + i0)*VP + h*HD;
        size_t ob1 = (size_t)(b*SEQ + i1)*VP + h*HD;
        #pragma unroll
        for (int nt = 0; nt < 8; nt++) {
            int cl = nt*8 + 2*qd;
            *(__half2*)&g_cath[ob0 + cl] = __float22half2_rn(make_float2(o[nt][0]*inv0, o[nt][1]*inv0));
            *(__half2*)&g_cath[ob1 + cl] = __float22half2_rn(make_float2(o[nt][2]*inv1, o[nt][3]*inv1));
        }
    } else {
        const int pb = (bz*32 + qb)*4 + chunk;
        float* po = g_part + (size_t)pb*4096;
        const int r0 = warp*16 + gq;
        const int r1 = r0 + 8;
        #pragma unroll
        for (int nt = 0; nt < 8; nt++) {
            int cl = nt*8 + 2*qd;
            *(float2*)&po[r0*64 + cl] = make_float2(o[nt][0], o[nt][1]);
            *(float2*)&po[r1*64 + cl] = make_float2(o[nt][2], o[nt][3]);
        }
        if (qd == 0) {
            float* ml = g_ml + (size_t)pb*128;
            ml[r0] = m0;  ml[64 + r0] = l0;
            ml[r1] = m1;  ml[64 + r1] = l1;
        }
    }
}

// ---------------- attention combine (qb >= 8) ----------------
__global__ void __launch_bounds__(256) attn_combine_kernel()
{
    const int qb = 8 + blockIdx.x;
    const int bz = blockIdx.y;
    const int h  = bz & 7;
    const int b  = bz >> 3;
    const int nc = qb/CHUNK_TILES + 1;
    const int tid = threadIdx.x;
    const int row = tid >> 2;
    const int dg  = (tid & 3) << 4;

    const int pb0 = (bz*32 + qb)*4;
    float mc[4], lc[4];
    float M = -INFINITY;
    for (int c = 0; c < nc; c++) {
        const float* ml = g_ml + (size_t)(pb0 + c)*128;
        mc[c] = ml[row];
        lc[c] = ml[64 + row];
        M = fmaxf(M, mc[c]);
    }
    float L = 0.f;
    float acc[16];
    #pragma unroll
    for (int i = 0; i < 16; i++) acc[i] = 0.f;
    for (int c = 0; c < nc; c++) {
        float w = __expf(mc[c] - M);
        L += lc[c]*w;
        const float* po = g_part + (size_t)(pb0 + c)*4096 + row*64 + dg;
        #pragma unroll
        for (int i = 0; i < 4; i++) {
            float4 v = *(const float4*)&po[i*4];
            acc[i*4+0] += v.x*w; acc[i*4+1] += v.y*w;
            acc[i*4+2] += v.z*w; acc[i*4+3] += v.w*w;
        }
    }
    float inv = 1.f / L;
    __half* dst = g_cath + (size_t)(b*SEQ + qb*64 + row)*VP + h*HD + dg;
    #pragma unroll
    for (int j = 0; j < 8; j++)
        *(__half2*)&dst[j*2] = __float22half2_rn(make_float2(acc[2*j]*inv, acc[2*j+1]*inv));
}

// ---------------- launch ----------------
extern "C" void kernel_launch(void* const* d_in, const int* in_sizes, int n_in,
                              void* d_out, int out_size)
{
    (void)in_sizes; (void)n_in; (void)out_size;
    const float* x     = (const float*)d_in[0];
    const float* gamma = (const float*)d_in[1];
    const float* beta  = (const float*)d_in[2];
    const float* w_in  = (const float*)d_in[3];
    const float* w_out = (const float*)d_in[4];
    const float* b_out = (const float*)d_in[5];
    float* out = (float*)d_out;

    __half *p_xth, *p_w1t, *p_w2t, *p_cath;
    float *p_part;
    cudaGetSymbolAddress((void**)&p_xth,  g_xth);
    cudaGetSymbolAddress((void**)&p_w1t,  g_w1t);
    cudaGetSymbolAddress((void**)&p_w2t,  g_w2t);
    cudaGetSymbolAddress((void**)&p_cath, g_cath);
    cudaGetSymbolAddress((void**)&p_part, g_part);

    // weight transpose + convert: w_in [512][3584] -> w1t [3584][512]; w_out [2560][512] -> w2t [512][2560]
    trans_cvt_kernel<<<dim3(HIDDEN/32, QKVP/32), 256>>>(w_in,  p_w1t, HIDDEN, QKVP);
    trans_cvt_kernel<<<dim3(VP/32, HIDDEN/32),   256>>>(w_out, p_w2t, VP, HIDDEN);

    ln_kernel<<<ROWS, 128>>>(x, gamma, beta);
    feat_kernel<<<(ROWS*128 + 255)/256, 256>>>();
    scan_kernel<<<BATCH*64, 256>>>();

    int gemm_smem = 4*ASTG*2;                               // 40960
    cudaFuncSetAttribute(hgemm_kernel<1>, cudaFuncAttributeMaxDynamicSharedMemorySize, gemm_smem);
    cudaFuncSetAttribute(hgemm_kernel<2>, cudaFuncAttributeMaxDynamicSharedMemorySize, gemm_smem);

    dim3 g1(QKVP/128, ROWS/128);     // (28, 32)
    hgemm_kernel<1><<<g1, 256, gemm_smem>>>(p_xth, p_w1t, nullptr, HIDDEN, HIDDEN, HIDDEN, QKVP);

    int attn_smem = 5*QTILE*2;                              // 46080
    cudaFuncSetAttribute(attn_mma_kernel, cudaFuncAttributeMaxDynamicSharedMemorySize, attn_smem);
    attn_mma_kernel<<<dim3(4, SEQ/64, BATCH*HEADS), 128, attn_smem>>>();
    attn_combine_kernel<<<dim3(24, BATCH*HEADS), 256>>>();

    dim3 g2(HIDDEN/128, ROWS/128, KSPLITS);  // (4, 32, 4)
    hgemm_kernel<2><<<g2, 256, gemm_smem>>>(p_cath, p_w2t, p_part, KSPLIT, VP, VP, HIDDEN);
    reduce_kernel<<<(ROWS*HIDDEN/4 + 255)/256, 256>>>(out, b_out);
}